// round 10
// baseline (speedup 1.0000x reference)
#include <cuda_runtime.h>
#include <cuda_bf16.h>
#include <math.h>
#include <stdint.h>

// ======================= compile-time structure constants =======================
struct Tables {
  signed char   ta[35][6];
  signed char   tb[35][6];
  float         ts[35][6];
  unsigned char p2i[256];
  unsigned char p2j[256];
};

constexpr Tables makeTables() {
  Tables T{};
  int c = 0;
  for (int x = 0; x < 7; x++)
    for (int y = x + 1; y < 7; y++)
      for (int z = y + 1; z < 7; z++) {
        int comp[4] = {0, 0, 0, 0};
        int m = 0;
        for (int e = 0; e < 7; e++)
          if (e != x && e != y && e != z) comp[m++] = e;
        int t = 0;
        for (int u = 0; u < 4; u++)
          for (int v = u + 1; v < 4; v++) {
            int a0 = comp[u], a1 = comp[v];
            int b0 = -1, b1 = -1;
            for (int e = 0; e < 4; e++) {
              if (e != u && e != v) { if (b0 < 0) b0 = comp[e]; else b1 = comp[e]; }
            }
            int perm[7] = {a0, a1, b0, b1, x, y, z};
            int inv = 0;
            for (int q = 0; q < 7; q++)
              for (int r = q + 1; r < 7; r++)
                if (perm[q] > perm[r]) inv++;
            T.ts[c][t] = (inv & 1) ? -1.0f : 1.0f;
            T.ta[c][t] = (signed char)(6 * a0 - a0 * (a0 - 1) / 2 + (a1 - a0 - 1));
            T.tb[c][t] = (signed char)(6 * b0 - b0 * (b0 - 1) / 2 + (b1 - b0 - 1));
            t++;
          }
        c++;
      }
  int p = 0;
  for (int i = 0; i < 21; i++)
    for (int j = i; j < 21; j++) {
      T.p2i[p] = (unsigned char)i;
      T.p2j[p] = (unsigned char)j;
      p++;
    }
  for (; p < 256; p++) { T.p2i[p] = 0; T.p2j[p] = 0; }
  return T;
}

constexpr Tables hT = makeTables();
__constant__ Tables dT = makeTables();

// ======================= device scratch =========================================
#define NMAX   4096
#define NGRID  148
#define NPAIR  231
#define NK     77
#define TLD    79
#define NRED   8

__device__ float g_w[NMAX];
__device__ float g_psum[64];
__device__ float g_invsum;
__device__ unsigned int g_cnt = 0;
__device__ float g_part[NGRID][256 * 80];
__device__ float g_S8[NRED][NPAIR * 80];
__device__ float g_S[NPAIR * NK];
__device__ float g_A[NK * NK];
__device__ float g_d[NK];
__device__ float g_e[NK];

// ======================= helpers ================================================
__device__ __forceinline__ uint32_t cvta_smem(const void* p) {
  uint32_t a;
  asm("{ .reg .u64 t; cvta.to.shared.u64 t, %1; cvt.u32.u64 %0, t; }"
      : "=r"(a) : "l"(p));
  return a;
}

__device__ __forceinline__ uint32_t bf16x2pack(float lo, float hi) {
  uint32_t r;
  asm("cvt.rn.bf16x2.f32 %0, %1, %2;" : "=r"(r) : "f"(hi), "f"(lo));
  return r;
}

#define LDSM_X4(r0, r1, r2, r3, addr) \
  asm volatile("ldmatrix.sync.aligned.m8n8.x4.shared.b16 {%0,%1,%2,%3}, [%4];" \
               : "=r"(r0), "=r"(r1), "=r"(r2), "=r"(r3) : "r"(addr))

#define MMA_BF16(c, a, b0_, b1_) \
  asm volatile("mma.sync.aligned.m16n8k16.row.col.f32.bf16.bf16.f32 " \
               "{%0,%1,%2,%3}, {%4,%5,%6,%7}, {%8,%9}, {%0,%1,%2,%3};" \
               : "+f"((c)[0]), "+f"((c)[1]), "+f"((c)[2]), "+f"((c)[3]) \
               : "r"((a)[0]), "r"((a)[1]), "r"((a)[2]), "r"((a)[3]), \
                 "r"(b0_), "r"(b1_))

// smem layout (bytes). Rows padded to 56 bf16 = 112 B (ldmatrix conflict-free).
// Double-buffered stage: [AH | AL | BH | BL | Ws]
#define A_ROWB    112
#define A_BYTES   (256 * A_ROWB)            // 28672
#define B_BYTES   (80 * A_ROWB)             // 8960
#define SOFF_AL   A_BYTES
#define SOFF_BH   (2 * A_BYTES)             // 57344
#define SOFF_BL   (2 * A_BYTES + B_BYTES)   // 66304
#define SOFF_WS   (2 * A_BYTES + 2 * B_BYTES)  // 75264
#define STG_BYTES (SOFF_WS + 1792)          // 77056
#define SMEM_MAIN (2 * STG_BYTES)           // 154112

// ======================= kernel 1: volumes + fused normalization sum ============
__global__ void __launch_bounds__(256, 1)
k_vols(const float* __restrict__ metric, int n) {
  __shared__ float red[256];
  __shared__ bool amLast;
  const int tid = threadIdx.x;
  const int idx = blockIdx.x * 256 + tid;
  float vol = 0.f;
  if (idx < n) {
    float a[7][7];
#pragma unroll
    for (int r = 0; r < 7; r++)
#pragma unroll
      for (int cc = 0; cc < 7; cc++) a[r][cc] = metric[idx * 49 + r * 7 + cc];
    float det = 1.f;
#pragma unroll
    for (int k = 0; k < 7; k++) {
      float mx = fabsf(a[k][k]);
      int piv = k;
#pragma unroll
      for (int r = k + 1; r < 7; r++) {
        float v = fabsf(a[r][k]);
        if (v > mx) { mx = v; piv = r; }
      }
#pragma unroll
      for (int r = k + 1; r < 7; r++) {
        if (piv == r) {
          det = -det;
#pragma unroll
          for (int cc = k; cc < 7; cc++) {
            float t = a[k][cc]; a[k][cc] = a[r][cc]; a[r][cc] = t;
          }
        }
      }
      float akk = a[k][k];
      det *= akk;
      float inv = (akk != 0.f) ? 1.f / akk : 0.f;
#pragma unroll
      for (int r = k + 1; r < 7; r++) {
        float f = a[r][k] * inv;
#pragma unroll
        for (int cc = k + 1; cc < 7; cc++) a[r][cc] = fmaf(-f, a[k][cc], a[r][cc]);
      }
    }
    vol = sqrtf(fabsf(det));
    g_w[idx] = vol;
  }
  red[tid] = vol;
  __syncthreads();
#pragma unroll
  for (int s = 128; s > 0; s >>= 1) {
    if (tid < s) red[tid] += red[tid + s];
    __syncthreads();
  }
  if (tid == 0) {
    g_psum[blockIdx.x] = red[0];
    __threadfence();
    unsigned int done = atomicAdd(&g_cnt, 1u);
    amLast = (done == gridDim.x - 1);
  }
  __syncthreads();
  if (amLast && tid == 0) {
    g_cnt = 0;
    float s = 0.f;
    for (unsigned int i = 0; i < gridDim.x; i++) s += g_psum[i];
    g_invsum = 1.f / s;
  }
}

// ======================= D-compute: fully unrolled ==============================
template <int C, int T>
__device__ __forceinline__ float dterms(const float (&wi)[21], const float (&wj)[21],
                                        float acc) {
  constexpr int a = hT.ta[C][T];
  constexpr int b = hT.tb[C][T];
  if constexpr (hT.ts[C][T] > 0.f)
    acc = fmaf(wi[a], wj[b], acc);
  else
    acc = fmaf(-wi[a], wj[b], acc);
  if constexpr (T + 1 < 6) return dterms<C, T + 1>(wi, wj, acc);
  return acc;
}

template <int C, int CBASE, int CEND>
__device__ __forceinline__ void dArr(float (&dv)[18], const float (&wi)[21],
                                     const float (&wj)[21]) {
  dv[C - CBASE] = dterms<C, 0>(wi, wj, 0.0f);
  if constexpr (C + 1 < CEND) dArr<C + 1, CBASE, CEND>(dv, wi, wj);
}

// ======================= kernel 2: mma.sync bf16-split GEMM (double-buffered) ===
// grid 148 x 512. Per n: stage Ws/B[buf] -> prefetch n+1 -> bar -> D-phase ->
// bar -> GEMM[buf]. Buffer parity removes WAR; stragglers overlap staging.
__global__ void __launch_bounds__(512, 1)
k_main(const float* __restrict__ omega, const float* __restrict__ Phi, int n,
       int chunk) {
  extern __shared__ char smc[];
  const int tid  = threadIdx.x;
  const int w    = tid >> 5;
  const int lane = tid & 31;
  const uint32_t smb = cvta_smem(smc);

  // zero both stages (k/n padding persists as zeros)
  for (int i = tid; i < SMEM_MAIN / 4; i += 512) ((uint32_t*)smc)[i] = 0u;

  int n0 = blockIdx.x * chunk;
  int n1 = n0 + chunk;
  if (n1 > n) n1 = n;

  if (n0 >= n1) {  // empty block: contribute zeros
    __syncthreads();
    for (int i = tid; i < 256 * 80; i += 512) g_part[blockIdx.x][i] = 0.f;
    return;
  }

  const int myPair = tid & 255;
  const int pi = dT.p2i[myPair];
  const int pj = dT.p2j[myPair];

  // B staging map: idx = tid + j*512 -> (kout, c); byte offset kout*112 + c*2
  uint32_t bOff[6];
  bool bAct[6];
#pragma unroll
  for (int j = 0; j < 6; j++) {
    int idx = tid + j * 512;
    bAct[j] = idx < 2695;
    int k = idx / 35;
    int c = idx - k * 35;
    bOff[j] = (uint32_t)(k * A_ROWB + c * 2);
  }

  // ldmatrix lane addresses for stage 0 (add STG_BYTES for stage 1)
  const uint32_t aRow  = (uint32_t)(w * 16 + ((lane >> 3) & 1) * 8 + (lane & 7));
  const uint32_t aAddr0 = smb + aRow * A_ROWB + (uint32_t)(lane >> 4) * 16;
  const uint32_t bRow  = (uint32_t)(((lane >> 4) & 1) * 8 + (lane & 7));
  const uint32_t bAddr0 = smb + SOFF_BH + bRow * A_ROWB +
                          (uint32_t)((lane >> 3) & 1) * 16;

  float acc[10][4];
#pragma unroll
  for (int a = 0; a < 10; a++)
#pragma unroll
    for (int b = 0; b < 4; b++) acc[a][b] = 0.f;

  // prefetch first n
  float rO = 0.f, rP[6], rWn = 0.f;
#pragma unroll
  for (int j = 0; j < 6; j++) rP[j] = 0.f;
  {
    const float* og = omega + (size_t)n0 * 441;
    if (tid < 441) rO = og[tid];
    const float* pg = Phi + (size_t)n0 * 2695;
#pragma unroll
    for (int j = 0; j < 6; j++)
      if (bAct[j]) rP[j] = pg[tid + j * 512];
    rWn = g_w[n0];
  }
  __syncthreads();  // zero-init visible

  int buf = 0;
#pragma unroll 1
  for (int nn = n0; nn < n1; nn++) {
    char* st = smc + (buf ? STG_BYTES : 0);
    float* Ws = (float*)(st + SOFF_WS);

    // ---- stage Ws + B from prefetched regs ----
    if (tid < 441) Ws[tid] = rO;
    {
      const float wn = rWn;
#pragma unroll
      for (int j = 0; j < 6; j++) {
        if (bAct[j]) {
          float v = rP[j] * wn;
          __nv_bfloat16 bh = __float2bfloat16(v);
          float res = v - __bfloat162float(bh);
          __nv_bfloat16 bl = __float2bfloat16(res);
          *(__nv_bfloat16*)(st + SOFF_BH + bOff[j]) = bh;
          *(__nv_bfloat16*)(st + SOFF_BL + bOff[j]) = bl;
        }
      }
    }

    // ---- prefetch next n (longest possible LDG->use distance) ----
    {
      int nx = (nn + 1 < n1) ? nn + 1 : nn;
      const float* og = omega + (size_t)nx * 441;
      if (tid < 441) rO = og[tid];
      const float* pg = Phi + (size_t)nx * 2695;
#pragma unroll
      for (int j = 0; j < 6; j++)
        if (bAct[j]) rP[j] = pg[tid + j * 512];
      rWn = g_w[nx];
    }
    __syncthreads();   // Ws/B visible; all warps past previous GEMM

    // ---- D-phase: fp32 -> bf16 hi/lo into A tiles ----
    {
      float wi[21], wj[21];
      const float* Wi = &Ws[pi * 21];
      const float* Wj = &Ws[pj * 21];
#pragma unroll
      for (int a = 0; a < 21; a++) { wi[a] = Wi[a]; wj[a] = Wj[a]; }
      float dv[18];
      int cb;
      if (tid < 256) { dArr<0, 0, 18>(dv, wi, wj); cb = 0; }
      else           { dArr<18, 18, 35>(dv, wi, wj); dv[17] = 0.f; cb = 18; }
      const uint32_t rowBase = (uint32_t)(myPair * A_ROWB + cb * 2);
#pragma unroll
      for (int u = 0; u < 9; u++) {
        float d0 = dv[2 * u], d1 = dv[2 * u + 1];
        uint32_t hw = bf16x2pack(d0, d1);
        float r0 = d0 - __uint_as_float(hw << 16);
        float r1 = d1 - __uint_as_float(hw & 0xffff0000u);
        uint32_t lw = bf16x2pack(r0, r1);
        uint32_t off = rowBase + 4 * u;
        *(uint32_t*)(st + off) = hw;
        *(uint32_t*)(st + SOFF_AL + off) = lw;
      }
    }
    __syncthreads();   // A visible

    // ---- GEMM on this buffer ----
    const uint32_t so = buf ? (uint32_t)STG_BYTES : 0u;
    const uint32_t aAddr = aAddr0 + so;
    const uint32_t bAddr = bAddr0 + so;
#pragma unroll
    for (int ks = 0; ks < 3; ks++) {
      uint32_t ah[4], al[4];
      LDSM_X4(ah[0], ah[1], ah[2], ah[3], aAddr + ks * 32);
      LDSM_X4(al[0], al[1], al[2], al[3], aAddr + A_BYTES + ks * 32);
#pragma unroll
      for (int tp = 0; tp < 5; tp++) {
        uint32_t bh[4], bl[4];
        uint32_t ba = bAddr + (uint32_t)(tp * 16 * A_ROWB) + ks * 32;
        LDSM_X4(bh[0], bh[1], bh[2], bh[3], ba);
        LDSM_X4(bl[0], bl[1], bl[2], bl[3], ba + B_BYTES);
        MMA_BF16(acc[2 * tp],     ah, bh[0], bh[1]);
        MMA_BF16(acc[2 * tp],     ah, bl[0], bl[1]);
        MMA_BF16(acc[2 * tp],     al, bh[0], bh[1]);
        MMA_BF16(acc[2 * tp + 1], ah, bh[2], bh[3]);
        MMA_BF16(acc[2 * tp + 1], ah, bl[2], bl[3]);
        MMA_BF16(acc[2 * tp + 1], al, bh[2], bh[3]);
      }
    }
    buf ^= 1;
  }

  // epilogue: spill register accumulators to g_part
  {
    const int g = lane >> 2, t = lane & 3;
    const int r0 = w * 16 + g, r1 = r0 + 8;
    float* dst = g_part[blockIdx.x];
#pragma unroll
    for (int nt = 0; nt < 10; nt++) {
      int col = nt * 8 + 2 * t;
      *(float2*)&dst[r0 * 80 + col] = make_float2(acc[nt][0], acc[nt][1]);
      *(float2*)&dst[r1 * 80 + col] = make_float2(acc[nt][2], acc[nt][3]);
    }
  }
}

// ======================= kernel 3a: reduce partials (8-way n-chunk) =============
__global__ void __launch_bounds__(128, 8)
k_reduceS() {
  const int t = blockIdx.x * 128 + threadIdx.x;
  if (t >= NPAIR * 20) return;
  const int p = t / 20;
  const int q = t - p * 20;
  const int y = blockIdx.y;
  const int b0  = (y < 4) ? y * 19 : 76 + (y - 4) * 18;
  const int cnt = (y < 4) ? 19 : 18;
  float4 s = make_float4(0.f, 0.f, 0.f, 0.f);
#pragma unroll 4
  for (int b = 0; b < cnt; b++) {
    float4 v = *(const float4*)&g_part[b0 + b][p * 80 + q * 4];
    s.x += v.x; s.y += v.y; s.z += v.z; s.w += v.w;
  }
  *(float4*)&g_S8[y][p * 80 + q * 4] = s;
}

// ======================= kernel 3b: emit Y + final S ============================
__global__ void k_emitY(float* __restrict__ out, int writeY) {
  int idx = blockIdx.x * blockDim.x + threadIdx.x;
  if (idx >= 441 * 77) return;
  const float inv = g_invsum;
  int i = idx / 1617;
  int rem = idx - i * 1617;
  int j = rem / 77;
  int k = rem - j * 77;
  int lo = i < j ? i : j;
  int hi = i < j ? j : i;
  int p = lo * 21 - lo * (lo - 1) / 2 + (hi - lo);
  int o = p * 80 + k;
  float s = ((g_S8[0][o] + g_S8[1][o]) + (g_S8[2][o] + g_S8[3][o])) +
            ((g_S8[4][o] + g_S8[5][o]) + (g_S8[6][o] + g_S8[7][o]));
  s *= inv;
  if (writeY) out[idx] = (j >= i) ? s : -s;
  if (i <= j) g_S[p * 77 + k] = s;
}

// ======================= kernel 4: build M = S^T diag(m) S ======================
__global__ void __launch_bounds__(128, 1)
k_buildM(float* __restrict__ out, int oM) {
  __shared__ float cs[NPAIR];
  const int k = blockIdx.x;
  const int tid = threadIdx.x;
  for (int p = tid; p < NPAIR; p += 128) {
    float wgt = (dT.p2i[p] == dT.p2j[p]) ? 1.f : 2.f;
    cs[p] = wgt * g_S[p * 77 + k];
  }
  __syncthreads();
  if (tid < 77) {
    float a0 = 0.f, a1 = 0.f, a2 = 0.f, a3 = 0.f;
    int p = 0;
#pragma unroll 4
    for (; p + 4 <= NPAIR; p += 4) {
      a0 = fmaf(cs[p],     g_S[p * 77 + tid],       a0);
      a1 = fmaf(cs[p + 1], g_S[(p + 1) * 77 + tid], a1);
      a2 = fmaf(cs[p + 2], g_S[(p + 2) * 77 + tid], a2);
      a3 = fmaf(cs[p + 3], g_S[(p + 3) * 77 + tid], a3);
    }
    for (; p < NPAIR; p++) a0 = fmaf(cs[p], g_S[p * 77 + tid], a0);
    float v = (a0 + a1) + (a2 + a3);
    out[oM + k * 77 + tid] = v;
    g_A[k * 77 + tid] = v;
  }
}

// ======================= kernel 5: Householder tridiagonalization ===============
__device__ __forceinline__ float blockReduce256(float v, volatile float* red,
                                                int tid) {
  __syncthreads();
#pragma unroll
  for (int o = 16; o; o >>= 1) v += __shfl_down_sync(0xffffffffu, v, o);
  if ((tid & 31) == 0) red[tid >> 5] = v;
  __syncthreads();
  if (tid < 8) {
    float r = red[tid];
#pragma unroll
    for (int o = 4; o; o >>= 1) r += __shfl_down_sync(0xffu, r, o);
    if (tid == 0) red[0] = r;
  }
  __syncthreads();
  return red[0];
}

__global__ void __launch_bounds__(256, 1) k_tridiag() {
  __shared__ float A[NK * TLD];
  __shared__ float us[80], ps[80], pp[80];
  __shared__ float red[8];
  __shared__ float dd[NK], ee[NK];
  __shared__ float scA, scTb;
  __shared__ int   skip;
  const int tid  = threadIdx.x;
  const int lane = tid & 31;
  const int warp = tid >> 5;
  const int rrow = tid >> 1;
  const int rq   = tid & 1;

  for (int idx = tid; idx < NK * NK; idx += 256) {
    int r = idx / NK, c = idx - r * NK;
    A[r * TLD + c] = g_A[idx];
  }
  __syncthreads();

#pragma unroll 1
  for (int k = 0; k < 75; k++) {
    const int m = 76 - k;
    float v = 0.f;
    if (tid < m) v = A[(k + 1 + tid) * TLD + k];
    float sigma = blockReduce256(v * v, red, tid);
    if (tid == 0) {
      dd[k] = A[k * TLD + k];
      if (sigma < 1e-30f) {
        ee[k] = 0.f;
        skip = 1;
      } else {
        float v0 = A[(k + 1) * TLD + k];
        float alpha = -copysignf(sqrtf(sigma), v0);
        ee[k] = alpha;
        scA = alpha;
        float beta = 2.f * (sigma - v0 * alpha);
        scTb = 2.f / beta;
        skip = 0;
      }
    }
    __syncthreads();
    if (skip) continue;

    if (tid < m) us[tid] = (tid == 0) ? v - scA : v;
    __syncthreads();

    {
      float a0 = 0.f, a1 = 0.f, a2 = 0.f, a3 = 0.f;
      if (rrow < m) {
        const float* row = &A[(k + 1 + rrow) * TLD + (k + 1)];
        int j = rq;
        for (; j + 6 < m; j += 8) {
          a0 = fmaf(row[j],     us[j],     a0);
          a1 = fmaf(row[j + 2], us[j + 2], a1);
          a2 = fmaf(row[j + 4], us[j + 4], a2);
          a3 = fmaf(row[j + 6], us[j + 6], a3);
        }
        for (; j < m; j += 2) a0 = fmaf(row[j], us[j], a0);
      }
      float s = (a0 + a1) + (a2 + a3);
      s += __shfl_xor_sync(0xffffffffu, s, 1);
      if (rrow < m && rq == 0) pp[rrow] = s * scTb;
    }
    __syncthreads();
    float upT = blockReduce256((tid < m) ? pp[tid] * us[tid] : 0.f, red, tid);
    if (tid < m) ps[tid] = pp[tid] - (upT * scTb * 0.5f) * us[tid];
    __syncthreads();

    for (int i = warp; i < m; i += 8) {
      const float ui = us[i], pi_ = ps[i];
      float* rowA = &A[(k + 1 + i) * TLD + (k + 1)];
      for (int j = lane; j < m; j += 32)
        rowA[j] -= ui * ps[j] + pi_ * us[j];
    }
    __syncthreads();
  }

  if (tid == 0) {
    dd[75] = A[75 * TLD + 75];
    ee[75] = A[76 * TLD + 75];
    dd[76] = A[76 * TLD + 76];
    ee[76] = 0.f;
  }
  __syncthreads();
  if (tid < NK) {
    g_d[tid] = dd[tid];
    g_e[tid] = ee[tid];
  }
}

// ======================= kernel 6: Sturm multisection eigenvalues ===============
#define NPROBE 13
#define NROUND 10

__global__ void __launch_bounds__(1024, 1)
k_bisect(float* __restrict__ out, int oE) {
  __shared__ float d_s[NK], e2_s[NK];
  __shared__ float lo_s[NK], hi_s[NK];
  __shared__ float xs[NK * NPROBE];
  __shared__ int   cs[NK * NPROBE];
  __shared__ float gl_s, gh_s, piv_s;
  const int tid = threadIdx.x;
  const int g = tid / NPROBE;
  const int j = tid - g * NPROBE;
  const bool act = (g < NK);

  if (tid < NK) {
    d_s[tid] = g_d[tid];
    float e = g_e[tid];
    e2_s[tid] = e * e;
  }
  __syncthreads();

  if (tid == 0) {
    float gl = 3.4e38f, gh = -3.4e38f, me2 = 0.f;
    for (int i = 0; i < NK; i++) {
      float eprev = (i > 0) ? sqrtf(e2_s[i - 1]) : 0.f;
      float ecur  = (i < 76) ? sqrtf(e2_s[i]) : 0.f;
      float r = eprev + ecur;
      gl = fminf(gl, d_s[i] - r);
      gh = fmaxf(gh, d_s[i] + r);
      me2 = fmaxf(me2, e2_s[i]);
    }
    float wid = fmaxf(gh - gl, 1e-20f);
    gl_s = gl - 1e-3f * wid;
    gh_s = gh + 1e-3f * wid;
    piv_s = fmaxf(me2 * 1.2e-38f, 1e-37f);
  }
  __syncthreads();
  if (tid < NK) { lo_s[tid] = gl_s; hi_s[tid] = gh_s; }
  __syncthreads();

  const float pivmin = piv_s;
  const float cj = (float)(j + 1) / (float)(NPROBE + 1);

#pragma unroll 1
  for (int r = 0; r < NROUND; r++) {
    if (act) {
      float lo = lo_s[g], hi = hi_s[g];
      float x = lo + (hi - lo) * cj;
      xs[tid] = x;
      float q = d_s[0] - x;
      int cnt = (q < 0.f);
#pragma unroll 4
      for (int i = 1; i < NK; i++) {
        float aq = fabsf(q);
        if (aq < pivmin) q = -pivmin;
        q = d_s[i] - x - __fdividef(e2_s[i - 1], q);
        cnt += (q < 0.f);
      }
      cs[tid] = cnt;
    }
    __syncthreads();
    if (act && j == 0) {
      float lo = lo_s[g], hi = hi_s[g];
      for (int jj = 0; jj < NPROBE; jj++) {
        int c = cs[g * NPROBE + jj];
        float x = xs[g * NPROBE + jj];
        if (c <= g) lo = x;
        else { hi = x; break; }
      }
      lo_s[g] = lo;
      hi_s[g] = hi;
    }
    __syncthreads();
  }

  if (act && j == 0) out[oE + (76 - g)] = 0.5f * (lo_s[g] + hi_s[g]);
}

// ======================= launch =================================================
extern "C" void kernel_launch(void* const* d_in, const int* in_sizes, int n_in,
                              void* d_out, int out_size) {
  const float* omega  = (const float*)d_in[0];
  const float* Phi    = (const float*)d_in[1];
  const float* metric = (const float*)d_in[2];
  int n = in_sizes[2] / 49;
  if (n > NMAX) n = NMAX;

  float* out = (float*)d_out;
  int oE = out_size - 77;
  int oM = oE - 77 * 77;
  int writeY = (out_size >= 33957 + 77 * 77 + 77) ? 1 : 0;

  int nb = (n + 255) / 256;
  k_vols<<<nb, 256>>>(metric, n);

  int chunk = (n + NGRID - 1) / NGRID;
  cudaFuncSetAttribute(k_main, cudaFuncAttributeMaxDynamicSharedMemorySize,
                       SMEM_MAIN);
  k_main<<<NGRID, 512, SMEM_MAIN>>>(omega, Phi, n, chunk);

  k_reduceS<<<dim3((NPAIR * 20 + 127) / 128, NRED), 128>>>();
  k_emitY<<<(441 * 77 + 255) / 256, 256>>>(out, writeY);

  k_buildM<<<77, 128>>>(out, oM);
  k_tridiag<<<1, 256>>>();
  k_bisect<<<1, 1024>>>(out, oE);
}

// round 11
// speedup vs baseline: 1.0506x; 1.0506x over previous
#include <cuda_runtime.h>
#include <cuda_bf16.h>
#include <math.h>
#include <stdint.h>

// ======================= compile-time structure constants =======================
struct Tables {
  signed char   ta[35][6];
  signed char   tb[35][6];
  float         ts[35][6];
  unsigned char p2i[256];
  unsigned char p2j[256];
};

constexpr Tables makeTables() {
  Tables T{};
  int c = 0;
  for (int x = 0; x < 7; x++)
    for (int y = x + 1; y < 7; y++)
      for (int z = y + 1; z < 7; z++) {
        int comp[4] = {0, 0, 0, 0};
        int m = 0;
        for (int e = 0; e < 7; e++)
          if (e != x && e != y && e != z) comp[m++] = e;
        int t = 0;
        for (int u = 0; u < 4; u++)
          for (int v = u + 1; v < 4; v++) {
            int a0 = comp[u], a1 = comp[v];
            int b0 = -1, b1 = -1;
            for (int e = 0; e < 4; e++) {
              if (e != u && e != v) { if (b0 < 0) b0 = comp[e]; else b1 = comp[e]; }
            }
            int perm[7] = {a0, a1, b0, b1, x, y, z};
            int inv = 0;
            for (int q = 0; q < 7; q++)
              for (int r = q + 1; r < 7; r++)
                if (perm[q] > perm[r]) inv++;
            T.ts[c][t] = (inv & 1) ? -1.0f : 1.0f;
            T.ta[c][t] = (signed char)(6 * a0 - a0 * (a0 - 1) / 2 + (a1 - a0 - 1));
            T.tb[c][t] = (signed char)(6 * b0 - b0 * (b0 - 1) / 2 + (b1 - b0 - 1));
            t++;
          }
        c++;
      }
  int p = 0;
  for (int i = 0; i < 21; i++)
    for (int j = i; j < 21; j++) {
      T.p2i[p] = (unsigned char)i;
      T.p2j[p] = (unsigned char)j;
      p++;
    }
  for (; p < 256; p++) { T.p2i[p] = 0; T.p2j[p] = 0; }
  return T;
}

constexpr Tables hT = makeTables();
__constant__ Tables dT = makeTables();

// ======================= device scratch =========================================
#define NMAX   4096
#define NGRID  148
#define NPAIR  231
#define NK     77
#define TLD    79
#define NRED   8

__device__ float g_w[NMAX];
__device__ float g_psum[64];
__device__ float g_invsum;
__device__ unsigned int g_cnt = 0;
__device__ float g_part[NGRID][256 * 80];
__device__ float g_S8[NRED][NPAIR * 80];
__device__ float g_S[NPAIR * NK];
__device__ float g_A[NK * NK];
__device__ float g_d[NK];
__device__ float g_e[NK];

// ======================= helpers ================================================
__device__ __forceinline__ uint32_t cvta_smem(const void* p) {
  uint32_t a;
  asm("{ .reg .u64 t; cvta.to.shared.u64 t, %1; cvt.u32.u64 %0, t; }"
      : "=r"(a) : "l"(p));
  return a;
}

__device__ __forceinline__ uint32_t bf16x2pack(float lo, float hi) {
  uint32_t r;
  asm("cvt.rn.bf16x2.f32 %0, %1, %2;" : "=r"(r) : "f"(hi), "f"(lo));
  return r;
}

#define LDSM_X4(r0, r1, r2, r3, addr) \
  asm volatile("ldmatrix.sync.aligned.m8n8.x4.shared.b16 {%0,%1,%2,%3}, [%4];" \
               : "=r"(r0), "=r"(r1), "=r"(r2), "=r"(r3) : "r"(addr))

#define MMA_BF16(c, a, b0_, b1_) \
  asm volatile("mma.sync.aligned.m16n8k16.row.col.f32.bf16.bf16.f32 " \
               "{%0,%1,%2,%3}, {%4,%5,%6,%7}, {%8,%9}, {%0,%1,%2,%3};" \
               : "+f"((c)[0]), "+f"((c)[1]), "+f"((c)[2]), "+f"((c)[3]) \
               : "r"((a)[0]), "r"((a)[1]), "r"((a)[2]), "r"((a)[3]), \
                 "r"(b0_), "r"(b1_))

// smem layout (bytes). Rows = 48 bf16 padded to 56 (112 B, 16B-aligned rows).
// A tiles warp-private single-buffered; B + Ws double-buffered.
#define A_ROWB    112
#define A_BYTES   (256 * A_ROWB)            // 28672 (AH at 0, AL at A_BYTES)
#define B_BYTES   (80 * A_ROWB)             // 8960
#define OFF_B     (2 * A_BYTES)             // 57344; per buf: [BH | BL]
#define OFF_WS    (OFF_B + 4 * B_BYTES)     // 93184; Ws[2][448]
#define SMEM_MAIN (OFF_WS + 2 * 448 * 4)    // 96768

// ======================= kernel 1: volumes + fused normalization sum ============
__global__ void __launch_bounds__(256, 1)
k_vols(const float* __restrict__ metric, int n) {
  __shared__ float red[256];
  __shared__ bool amLast;
  const int tid = threadIdx.x;
  const int idx = blockIdx.x * 256 + tid;
  float vol = 0.f;
  if (idx < n) {
    float a[7][7];
#pragma unroll
    for (int r = 0; r < 7; r++)
#pragma unroll
      for (int cc = 0; cc < 7; cc++) a[r][cc] = metric[idx * 49 + r * 7 + cc];
    float det = 1.f;
#pragma unroll
    for (int k = 0; k < 7; k++) {
      float mx = fabsf(a[k][k]);
      int piv = k;
#pragma unroll
      for (int r = k + 1; r < 7; r++) {
        float v = fabsf(a[r][k]);
        if (v > mx) { mx = v; piv = r; }
      }
#pragma unroll
      for (int r = k + 1; r < 7; r++) {
        if (piv == r) {
          det = -det;
#pragma unroll
          for (int cc = k; cc < 7; cc++) {
            float t = a[k][cc]; a[k][cc] = a[r][cc]; a[r][cc] = t;
          }
        }
      }
      float akk = a[k][k];
      det *= akk;
      float inv = (akk != 0.f) ? 1.f / akk : 0.f;
#pragma unroll
      for (int r = k + 1; r < 7; r++) {
        float f = a[r][k] * inv;
#pragma unroll
        for (int cc = k + 1; cc < 7; cc++) a[r][cc] = fmaf(-f, a[k][cc], a[r][cc]);
      }
    }
    vol = sqrtf(fabsf(det));
    g_w[idx] = vol;
  }
  red[tid] = vol;
  __syncthreads();
#pragma unroll
  for (int s = 128; s > 0; s >>= 1) {
    if (tid < s) red[tid] += red[tid + s];
    __syncthreads();
  }
  if (tid == 0) {
    g_psum[blockIdx.x] = red[0];
    __threadfence();
    unsigned int done = atomicAdd(&g_cnt, 1u);
    amLast = (done == gridDim.x - 1);
  }
  __syncthreads();
  if (amLast && tid == 0) {
    g_cnt = 0;
    float s = 0.f;
    for (unsigned int i = 0; i < gridDim.x; i++) s += g_psum[i];
    g_invsum = 1.f / s;
  }
}

// ======================= D-compute: fully unrolled ==============================
template <int C, int T>
__device__ __forceinline__ float dterms(const float (&wi)[21], const float (&wj)[21],
                                        float acc) {
  constexpr int a = hT.ta[C][T];
  constexpr int b = hT.tb[C][T];
  if constexpr (hT.ts[C][T] > 0.f)
    acc = fmaf(wi[a], wj[b], acc);
  else
    acc = fmaf(-wi[a], wj[b], acc);
  if constexpr (T + 1 < 6) return dterms<C, T + 1>(wi, wj, acc);
  return acc;
}

template <int C, int CBASE, int CEND>
__device__ __forceinline__ void dArr(float (&dv)[18], const float (&wi)[21],
                                     const float (&wj)[21]) {
  dv[C - CBASE] = dterms<C, 0>(wi, wj, 0.0f);
  if constexpr (C + 1 < CEND) dArr<C + 1, CBASE, CEND>(dv, wi, wj);
}

// ======================= kernel 2: mma.sync bf16-split GEMM =====================
// grid 148 x 512. A tiles warp-private (lane 0-15: c[0,18) of own 16 pairs,
// lane 16-31: c[18,35)); B/Ws double-buffered -> ONE block barrier per n.
__global__ void __launch_bounds__(512, 1)
k_main(const float* __restrict__ omega, const float* __restrict__ Phi, int n,
       int chunk) {
  extern __shared__ char smc[];
  const int tid  = threadIdx.x;
  const int w    = tid >> 5;
  const int lane = tid & 31;
  const uint32_t smb = cvta_smem(smc);

  // zero all tiles once (k/n padding persists as zeros)
  for (int i = tid; i < SMEM_MAIN / 4; i += 512) ((uint32_t*)smc)[i] = 0u;

  int n0 = blockIdx.x * chunk;
  int n1 = n0 + chunk;
  if (n1 > n) n1 = n;

  if (n0 >= n1) {  // empty block: contribute zeros
    __syncthreads();
    for (int i = tid; i < 256 * 80; i += 512) g_part[blockIdx.x][i] = 0.f;
    return;
  }

  // warp-private D assignment: pair = w*16 + (lane&15), c-half = lane>>4
  const int myPair = w * 16 + (lane & 15);
  const int pi = dT.p2i[myPair];
  const int pj = dT.p2j[myPair];
  const int halfHi = lane >> 4;

  // B staging map: idx = tid + j*512 -> (kout, c); byte offset kout*112 + c*2
  uint32_t bOff[6];
  bool bAct[6];
#pragma unroll
  for (int j = 0; j < 6; j++) {
    int idx = tid + j * 512;
    bAct[j] = idx < 2695;
    int k = idx / 35;
    int c = idx - k * 35;
    bOff[j] = (uint32_t)(k * A_ROWB + c * 2);
  }

  // ldmatrix lane addresses (A fixed; B per buffer)
  const uint32_t aRow  = (uint32_t)(w * 16 + ((lane >> 3) & 1) * 8 + (lane & 7));
  const uint32_t aAddr = smb + aRow * A_ROWB + (uint32_t)(lane >> 4) * 16;
  const uint32_t bRow  = (uint32_t)(((lane >> 4) & 1) * 8 + (lane & 7));
  const uint32_t bAddr0 = smb + OFF_B + bRow * A_ROWB +
                          (uint32_t)((lane >> 3) & 1) * 16;

  float acc[10][4];
#pragma unroll
  for (int a = 0; a < 10; a++)
#pragma unroll
    for (int b = 0; b < 4; b++) acc[a][b] = 0.f;

  // prefetch first n
  float rO = 0.f, rP[6], rWn = 0.f;
#pragma unroll
  for (int j = 0; j < 6; j++) rP[j] = 0.f;
  {
    const float* og = omega + (size_t)n0 * 441;
    if (tid < 441) rO = og[tid];
    const float* pg = Phi + (size_t)n0 * 2695;
#pragma unroll
    for (int j = 0; j < 6; j++)
      if (bAct[j]) rP[j] = pg[tid + j * 512];
    rWn = g_w[n0];
  }
  __syncthreads();  // zero-init visible

  int buf = 0;
#pragma unroll 1
  for (int nn = n0; nn < n1; nn++) {
    char* bb = smc + OFF_B + (buf ? 2 * B_BYTES : 0);
    float* Ws = (float*)(smc + OFF_WS) + (buf ? 448 : 0);

    // ---- stage Ws + B[buf] from prefetched regs ----
    if (tid < 441) Ws[tid] = rO;
    {
      const float wn = rWn;
#pragma unroll
      for (int j = 0; j < 6; j++) {
        if (bAct[j]) {
          float v = rP[j] * wn;
          __nv_bfloat16 bh = __float2bfloat16(v);
          float res = v - __bfloat162float(bh);
          __nv_bfloat16 bl = __float2bfloat16(res);
          *(__nv_bfloat16*)(bb + bOff[j]) = bh;
          *(__nv_bfloat16*)(bb + B_BYTES + bOff[j]) = bl;
        }
      }
    }

    // ---- prefetch next n ----
    {
      int nx = (nn + 1 < n1) ? nn + 1 : nn;
      const float* og = omega + (size_t)nx * 441;
      if (tid < 441) rO = og[tid];
      const float* pg = Phi + (size_t)nx * 2695;
#pragma unroll
      for (int j = 0; j < 6; j++)
        if (bAct[j]) rP[j] = pg[tid + j * 512];
      rWn = g_w[nx];
    }
    __syncthreads();   // the ONE block barrier: Ws/B[buf] visible to all

    // ---- D-phase: warp-private A tiles (fp32 -> bf16 hi/lo) ----
    __syncwarp();      // order prior GEMM's LDSM before overwriting own A rows
    {
      float wi[21], wj[21];
      const float* Wi = &Ws[pi * 21];
      const float* Wj = &Ws[pj * 21];
#pragma unroll
      for (int a = 0; a < 21; a++) { wi[a] = Wi[a]; wj[a] = Wj[a]; }
      float dv[18];
      int cb;
      if (!halfHi) { dArr<0, 0, 18>(dv, wi, wj); cb = 0; }
      else         { dArr<18, 18, 35>(dv, wi, wj); dv[17] = 0.f; cb = 18; }
      const uint32_t rowBase = (uint32_t)(myPair * A_ROWB + cb * 2);
#pragma unroll
      for (int u = 0; u < 9; u++) {
        float d0 = dv[2 * u], d1 = dv[2 * u + 1];
        uint32_t hw = bf16x2pack(d0, d1);
        float r0 = d0 - __uint_as_float(hw << 16);
        float r1 = d1 - __uint_as_float(hw & 0xffff0000u);
        uint32_t lw = bf16x2pack(r0, r1);
        uint32_t off = rowBase + 4 * u;
        *(uint32_t*)(smc + off) = hw;
        *(uint32_t*)(smc + A_BYTES + off) = lw;
      }
    }
    __syncwarp();      // own A writes visible to own ldmatrix

    // ---- GEMM: own A tile x B[buf] ----
    const uint32_t bAddr = bAddr0 + (buf ? (uint32_t)(2 * B_BYTES) : 0u);
#pragma unroll
    for (int ks = 0; ks < 3; ks++) {
      uint32_t ah[4], al[4];
      LDSM_X4(ah[0], ah[1], ah[2], ah[3], aAddr + ks * 32);
      LDSM_X4(al[0], al[1], al[2], al[3], aAddr + A_BYTES + ks * 32);
#pragma unroll
      for (int tp = 0; tp < 5; tp++) {
        uint32_t bh[4], bl[4];
        uint32_t ba = bAddr + (uint32_t)(tp * 16 * A_ROWB) + ks * 32;
        LDSM_X4(bh[0], bh[1], bh[2], bh[3], ba);
        LDSM_X4(bl[0], bl[1], bl[2], bl[3], ba + B_BYTES);
        MMA_BF16(acc[2 * tp],     ah, bh[0], bh[1]);
        MMA_BF16(acc[2 * tp],     ah, bl[0], bl[1]);
        MMA_BF16(acc[2 * tp],     al, bh[0], bh[1]);
        MMA_BF16(acc[2 * tp + 1], ah, bh[2], bh[3]);
        MMA_BF16(acc[2 * tp + 1], ah, bl[2], bl[3]);
        MMA_BF16(acc[2 * tp + 1], al, bh[2], bh[3]);
      }
    }
    buf ^= 1;
  }

  // epilogue: spill register accumulators to g_part
  {
    const int g = lane >> 2, t = lane & 3;
    const int r0 = w * 16 + g, r1 = r0 + 8;
    float* dst = g_part[blockIdx.x];
#pragma unroll
    for (int nt = 0; nt < 10; nt++) {
      int col = nt * 8 + 2 * t;
      *(float2*)&dst[r0 * 80 + col] = make_float2(acc[nt][0], acc[nt][1]);
      *(float2*)&dst[r1 * 80 + col] = make_float2(acc[nt][2], acc[nt][3]);
    }
  }
}

// ======================= kernel 3a: reduce partials (8-way n-chunk) =============
__global__ void __launch_bounds__(128, 8)
k_reduceS() {
  const int t = blockIdx.x * 128 + threadIdx.x;
  if (t >= NPAIR * 20) return;
  const int p = t / 20;
  const int q = t - p * 20;
  const int y = blockIdx.y;
  const int b0  = (y < 4) ? y * 19 : 76 + (y - 4) * 18;
  const int cnt = (y < 4) ? 19 : 18;
  float4 s = make_float4(0.f, 0.f, 0.f, 0.f);
#pragma unroll 4
  for (int b = 0; b < cnt; b++) {
    float4 v = *(const float4*)&g_part[b0 + b][p * 80 + q * 4];
    s.x += v.x; s.y += v.y; s.z += v.z; s.w += v.w;
  }
  *(float4*)&g_S8[y][p * 80 + q * 4] = s;
}

// ======================= kernel 3b: emit Y + final S ============================
__global__ void k_emitY(float* __restrict__ out, int writeY) {
  int idx = blockIdx.x * blockDim.x + threadIdx.x;
  if (idx >= 441 * 77) return;
  const float inv = g_invsum;
  int i = idx / 1617;
  int rem = idx - i * 1617;
  int j = rem / 77;
  int k = rem - j * 77;
  int lo = i < j ? i : j;
  int hi = i < j ? j : i;
  int p = lo * 21 - lo * (lo - 1) / 2 + (hi - lo);
  int o = p * 80 + k;
  float s = ((g_S8[0][o] + g_S8[1][o]) + (g_S8[2][o] + g_S8[3][o])) +
            ((g_S8[4][o] + g_S8[5][o]) + (g_S8[6][o] + g_S8[7][o]));
  s *= inv;
  if (writeY) out[idx] = (j >= i) ? s : -s;
  if (i <= j) g_S[p * 77 + k] = s;
}

// ======================= kernel 4: build M = S^T diag(m) S ======================
__global__ void __launch_bounds__(128, 1)
k_buildM(float* __restrict__ out, int oM) {
  __shared__ float cs[NPAIR];
  const int k = blockIdx.x;
  const int tid = threadIdx.x;
  for (int p = tid; p < NPAIR; p += 128) {
    float wgt = (dT.p2i[p] == dT.p2j[p]) ? 1.f : 2.f;
    cs[p] = wgt * g_S[p * 77 + k];
  }
  __syncthreads();
  if (tid < 77) {
    float a0 = 0.f, a1 = 0.f, a2 = 0.f, a3 = 0.f;
    int p = 0;
#pragma unroll 4
    for (; p + 4 <= NPAIR; p += 4) {
      a0 = fmaf(cs[p],     g_S[p * 77 + tid],       a0);
      a1 = fmaf(cs[p + 1], g_S[(p + 1) * 77 + tid], a1);
      a2 = fmaf(cs[p + 2], g_S[(p + 2) * 77 + tid], a2);
      a3 = fmaf(cs[p + 3], g_S[(p + 3) * 77 + tid], a3);
    }
    for (; p < NPAIR; p++) a0 = fmaf(cs[p], g_S[p * 77 + tid], a0);
    float v = (a0 + a1) + (a2 + a3);
    out[oM + k * 77 + tid] = v;
    g_A[k * 77 + tid] = v;
  }
}

// ======================= kernel 5: Householder tridiagonalization ===============
__device__ __forceinline__ float blockReduce256(float v, volatile float* red,
                                                int tid) {
  __syncthreads();
#pragma unroll
  for (int o = 16; o; o >>= 1) v += __shfl_down_sync(0xffffffffu, v, o);
  if ((tid & 31) == 0) red[tid >> 5] = v;
  __syncthreads();
  if (tid < 8) {
    float r = red[tid];
#pragma unroll
    for (int o = 4; o; o >>= 1) r += __shfl_down_sync(0xffu, r, o);
    if (tid == 0) red[0] = r;
  }
  __syncthreads();
  return red[0];
}

__global__ void __launch_bounds__(256, 1) k_tridiag() {
  __shared__ float A[NK * TLD];
  __shared__ float us[80], ps[80], pp[80];
  __shared__ float red[8];
  __shared__ float dd[NK], ee[NK];
  __shared__ float scA, scTb;
  __shared__ int   skip;
  const int tid  = threadIdx.x;
  const int lane = tid & 31;
  const int warp = tid >> 5;
  const int rrow = tid >> 1;
  const int rq   = tid & 1;

  for (int idx = tid; idx < NK * NK; idx += 256) {
    int r = idx / NK, c = idx - r * NK;
    A[r * TLD + c] = g_A[idx];
  }
  __syncthreads();

#pragma unroll 1
  for (int k = 0; k < 75; k++) {
    const int m = 76 - k;
    float v = 0.f;
    if (tid < m) v = A[(k + 1 + tid) * TLD + k];
    float sigma = blockReduce256(v * v, red, tid);
    if (tid == 0) {
      dd[k] = A[k * TLD + k];
      if (sigma < 1e-30f) {
        ee[k] = 0.f;
        skip = 1;
      } else {
        float v0 = A[(k + 1) * TLD + k];
        float alpha = -copysignf(sqrtf(sigma), v0);
        ee[k] = alpha;
        scA = alpha;
        float beta = 2.f * (sigma - v0 * alpha);
        scTb = 2.f / beta;
        skip = 0;
      }
    }
    __syncthreads();
    if (skip) continue;

    if (tid < m) us[tid] = (tid == 0) ? v - scA : v;
    __syncthreads();

    {
      float a0 = 0.f, a1 = 0.f, a2 = 0.f, a3 = 0.f;
      if (rrow < m) {
        const float* row = &A[(k + 1 + rrow) * TLD + (k + 1)];
        int j = rq;
        for (; j + 6 < m; j += 8) {
          a0 = fmaf(row[j],     us[j],     a0);
          a1 = fmaf(row[j + 2], us[j + 2], a1);
          a2 = fmaf(row[j + 4], us[j + 4], a2);
          a3 = fmaf(row[j + 6], us[j + 6], a3);
        }
        for (; j < m; j += 2) a0 = fmaf(row[j], us[j], a0);
      }
      float s = (a0 + a1) + (a2 + a3);
      s += __shfl_xor_sync(0xffffffffu, s, 1);
      if (rrow < m && rq == 0) pp[rrow] = s * scTb;
    }
    __syncthreads();
    float upT = blockReduce256((tid < m) ? pp[tid] * us[tid] : 0.f, red, tid);
    if (tid < m) ps[tid] = pp[tid] - (upT * scTb * 0.5f) * us[tid];
    __syncthreads();

    for (int i = warp; i < m; i += 8) {
      const float ui = us[i], pi_ = ps[i];
      float* rowA = &A[(k + 1 + i) * TLD + (k + 1)];
      for (int j = lane; j < m; j += 32)
        rowA[j] -= ui * ps[j] + pi_ * us[j];
    }
    __syncthreads();
  }

  if (tid == 0) {
    dd[75] = A[75 * TLD + 75];
    ee[75] = A[76 * TLD + 75];
    dd[76] = A[76 * TLD + 76];
    ee[76] = 0.f;
  }
  __syncthreads();
  if (tid < NK) {
    g_d[tid] = dd[tid];
    g_e[tid] = ee[tid];
  }
}

// ======================= kernel 6: Sturm multisection eigenvalues ===============
#define NPROBE 13
#define NROUND 10

__global__ void __launch_bounds__(1024, 1)
k_bisect(float* __restrict__ out, int oE) {
  __shared__ float d_s[NK], e2_s[NK];
  __shared__ float lo_s[NK], hi_s[NK];
  __shared__ float xs[NK * NPROBE];
  __shared__ int   cs[NK * NPROBE];
  __shared__ float gl_s, gh_s, piv_s;
  const int tid = threadIdx.x;
  const int g = tid / NPROBE;
  const int j = tid - g * NPROBE;
  const bool act = (g < NK);

  if (tid < NK) {
    d_s[tid] = g_d[tid];
    float e = g_e[tid];
    e2_s[tid] = e * e;
  }
  __syncthreads();

  if (tid == 0) {
    float gl = 3.4e38f, gh = -3.4e38f, me2 = 0.f;
    for (int i = 0; i < NK; i++) {
      float eprev = (i > 0) ? sqrtf(e2_s[i - 1]) : 0.f;
      float ecur  = (i < 76) ? sqrtf(e2_s[i]) : 0.f;
      float r = eprev + ecur;
      gl = fminf(gl, d_s[i] - r);
      gh = fmaxf(gh, d_s[i] + r);
      me2 = fmaxf(me2, e2_s[i]);
    }
    float wid = fmaxf(gh - gl, 1e-20f);
    gl_s = gl - 1e-3f * wid;
    gh_s = gh + 1e-3f * wid;
    piv_s = fmaxf(me2 * 1.2e-38f, 1e-37f);
  }
  __syncthreads();
  if (tid < NK) { lo_s[tid] = gl_s; hi_s[tid] = gh_s; }
  __syncthreads();

  const float pivmin = piv_s;
  const float cj = (float)(j + 1) / (float)(NPROBE + 1);

#pragma unroll 1
  for (int r = 0; r < NROUND; r++) {
    if (act) {
      float lo = lo_s[g], hi = hi_s[g];
      float x = lo + (hi - lo) * cj;
      xs[tid] = x;
      float q = d_s[0] - x;
      int cnt = (q < 0.f);
#pragma unroll 4
      for (int i = 1; i < NK; i++) {
        float aq = fabsf(q);
        if (aq < pivmin) q = -pivmin;
        q = d_s[i] - x - __fdividef(e2_s[i - 1], q);
        cnt += (q < 0.f);
      }
      cs[tid] = cnt;
    }
    __syncthreads();
    if (act && j == 0) {
      float lo = lo_s[g], hi = hi_s[g];
      for (int jj = 0; jj < NPROBE; jj++) {
        int c = cs[g * NPROBE + jj];
        float x = xs[g * NPROBE + jj];
        if (c <= g) lo = x;
        else { hi = x; break; }
      }
      lo_s[g] = lo;
      hi_s[g] = hi;
    }
    __syncthreads();
  }

  if (act && j == 0) out[oE + (76 - g)] = 0.5f * (lo_s[g] + hi_s[g]);
}

// ======================= launch =================================================
extern "C" void kernel_launch(void* const* d_in, const int* in_sizes, int n_in,
                              void* d_out, int out_size) {
  const float* omega  = (const float*)d_in[0];
  const float* Phi    = (const float*)d_in[1];
  const float* metric = (const float*)d_in[2];
  int n = in_sizes[2] / 49;
  if (n > NMAX) n = NMAX;

  float* out = (float*)d_out;
  int oE = out_size - 77;
  int oM = oE - 77 * 77;
  int writeY = (out_size >= 33957 + 77 * 77 + 77) ? 1 : 0;

  int nb = (n + 255) / 256;
  k_vols<<<nb, 256>>>(metric, n);

  int chunk = (n + NGRID - 1) / NGRID;
  cudaFuncSetAttribute(k_main, cudaFuncAttributeMaxDynamicSharedMemorySize,
                       SMEM_MAIN);
  k_main<<<NGRID, 512, SMEM_MAIN>>>(omega, Phi, n, chunk);

  k_reduceS<<<dim3((NPAIR * 20 + 127) / 128, NRED), 128>>>();
  k_emitY<<<(441 * 77 + 255) / 256, 256>>>(out, writeY);

  k_buildM<<<77, 128>>>(out, oM);
  k_tridiag<<<1, 256>>>();
  k_bisect<<<1, 1024>>>(out, oE);
}

// round 12
// speedup vs baseline: 1.0556x; 1.0048x over previous
#include <cuda_runtime.h>
#include <cuda_bf16.h>
#include <math.h>
#include <stdint.h>

// ======================= compile-time structure constants =======================
struct Tables {
  signed char   ta[35][6];
  signed char   tb[35][6];
  float         ts[35][6];
  unsigned char p2i[256];
  unsigned char p2j[256];
};

constexpr Tables makeTables() {
  Tables T{};
  int c = 0;
  for (int x = 0; x < 7; x++)
    for (int y = x + 1; y < 7; y++)
      for (int z = y + 1; z < 7; z++) {
        int comp[4] = {0, 0, 0, 0};
        int m = 0;
        for (int e = 0; e < 7; e++)
          if (e != x && e != y && e != z) comp[m++] = e;
        int t = 0;
        for (int u = 0; u < 4; u++)
          for (int v = u + 1; v < 4; v++) {
            int a0 = comp[u], a1 = comp[v];
            int b0 = -1, b1 = -1;
            for (int e = 0; e < 4; e++) {
              if (e != u && e != v) { if (b0 < 0) b0 = comp[e]; else b1 = comp[e]; }
            }
            int perm[7] = {a0, a1, b0, b1, x, y, z};
            int inv = 0;
            for (int q = 0; q < 7; q++)
              for (int r = q + 1; r < 7; r++)
                if (perm[q] > perm[r]) inv++;
            T.ts[c][t] = (inv & 1) ? -1.0f : 1.0f;
            T.ta[c][t] = (signed char)(6 * a0 - a0 * (a0 - 1) / 2 + (a1 - a0 - 1));
            T.tb[c][t] = (signed char)(6 * b0 - b0 * (b0 - 1) / 2 + (b1 - b0 - 1));
            t++;
          }
        c++;
      }
  int p = 0;
  for (int i = 0; i < 21; i++)
    for (int j = i; j < 21; j++) {
      T.p2i[p] = (unsigned char)i;
      T.p2j[p] = (unsigned char)j;
      p++;
    }
  for (; p < 256; p++) { T.p2i[p] = 0; T.p2j[p] = 0; }
  return T;
}

constexpr Tables hT = makeTables();
__constant__ Tables dT = makeTables();

// ======================= device scratch =========================================
#define NMAX   4096
#define NGRID  148
#define NPAIR  231
#define NK     77
#define TLD    79
#define NRED   8

__device__ float g_w[NMAX];
__device__ float g_psum[64];
__device__ float g_invsum;
__device__ unsigned int g_cnt = 0;
__device__ float g_part[NGRID][256 * 80];
__device__ float g_S8[NRED][NPAIR * 80];
__device__ float g_S[NPAIR * NK];
__device__ float g_A[NK * NK];
__device__ float g_d[NK];
__device__ float g_e[NK];

// ======================= helpers ================================================
__device__ __forceinline__ uint32_t cvta_smem(const void* p) {
  uint32_t a;
  asm("{ .reg .u64 t; cvta.to.shared.u64 t, %1; cvt.u32.u64 %0, t; }"
      : "=r"(a) : "l"(p));
  return a;
}

__device__ __forceinline__ uint32_t bf16x2pack(float lo, float hi) {
  uint32_t r;
  asm("cvt.rn.bf16x2.f32 %0, %1, %2;" : "=r"(r) : "f"(hi), "f"(lo));
  return r;
}

#define LDSM_X4(r0, r1, r2, r3, addr) \
  asm volatile("ldmatrix.sync.aligned.m8n8.x4.shared.b16 {%0,%1,%2,%3}, [%4];" \
               : "=r"(r0), "=r"(r1), "=r"(r2), "=r"(r3) : "r"(addr))

#define MMA_BF16(c, a, b0_, b1_) \
  asm volatile("mma.sync.aligned.m16n8k16.row.col.f32.bf16.bf16.f32 " \
               "{%0,%1,%2,%3}, {%4,%5,%6,%7}, {%8,%9}, {%0,%1,%2,%3};" \
               : "+f"((c)[0]), "+f"((c)[1]), "+f"((c)[2]), "+f"((c)[3]) \
               : "r"((a)[0]), "r"((a)[1]), "r"((a)[2]), "r"((a)[3]), \
                 "r"(b0_), "r"(b1_))

// smem layout (bytes). Tensor K = 32 c (64 B data) padded to 80 B rows
// (20r mod 32 distinct -> ldmatrix conflict-free). fp32 tail: 3 c.
#define AROW      80
#define A_BYTES   (256 * AROW)              // 20480 (AH at 0, AL at A_BYTES)
#define B_BYTES   (80 * AROW)               // 6400
#define OFF_B     (2 * A_BYTES)             // 40960; per buf [BH|BL], 2 bufs
#define OFF_PF    (OFF_B + 4 * B_BYTES)     // 66560; fp32 P, 2 bufs x 240 floats
#define OFF_DS    (OFF_PF + 2 * 240 * 4)    // 68480; Ds32[3][256] floats
#define OFF_WS    (OFF_DS + 3 * 256 * 4)    // 71552; Ws[2][448] floats
#define SMEM_MAIN (OFF_WS + 2 * 448 * 4)    // 75136

// ======================= kernel 1: volumes + fused normalization sum ============
__global__ void __launch_bounds__(256, 1)
k_vols(const float* __restrict__ metric, int n) {
  __shared__ float red[256];
  __shared__ bool amLast;
  const int tid = threadIdx.x;
  const int idx = blockIdx.x * 256 + tid;
  float vol = 0.f;
  if (idx < n) {
    float a[7][7];
#pragma unroll
    for (int r = 0; r < 7; r++)
#pragma unroll
      for (int cc = 0; cc < 7; cc++) a[r][cc] = metric[idx * 49 + r * 7 + cc];
    float det = 1.f;
#pragma unroll
    for (int k = 0; k < 7; k++) {
      float mx = fabsf(a[k][k]);
      int piv = k;
#pragma unroll
      for (int r = k + 1; r < 7; r++) {
        float v = fabsf(a[r][k]);
        if (v > mx) { mx = v; piv = r; }
      }
#pragma unroll
      for (int r = k + 1; r < 7; r++) {
        if (piv == r) {
          det = -det;
#pragma unroll
          for (int cc = k; cc < 7; cc++) {
            float t = a[k][cc]; a[k][cc] = a[r][cc]; a[r][cc] = t;
          }
        }
      }
      float akk = a[k][k];
      det *= akk;
      float inv = (akk != 0.f) ? 1.f / akk : 0.f;
#pragma unroll
      for (int r = k + 1; r < 7; r++) {
        float f = a[r][k] * inv;
#pragma unroll
        for (int cc = k + 1; cc < 7; cc++) a[r][cc] = fmaf(-f, a[k][cc], a[r][cc]);
      }
    }
    vol = sqrtf(fabsf(det));
    g_w[idx] = vol;
  }
  red[tid] = vol;
  __syncthreads();
#pragma unroll
  for (int s = 128; s > 0; s >>= 1) {
    if (tid < s) red[tid] += red[tid + s];
    __syncthreads();
  }
  if (tid == 0) {
    g_psum[blockIdx.x] = red[0];
    __threadfence();
    unsigned int done = atomicAdd(&g_cnt, 1u);
    amLast = (done == gridDim.x - 1);
  }
  __syncthreads();
  if (amLast && tid == 0) {
    g_cnt = 0;
    float s = 0.f;
    for (unsigned int i = 0; i < gridDim.x; i++) s += g_psum[i];
    g_invsum = 1.f / s;
  }
}

// ======================= D-compute: fully unrolled ==============================
template <int C, int T>
__device__ __forceinline__ float dterms(const float (&wi)[21], const float (&wj)[21],
                                        float acc) {
  constexpr int a = hT.ta[C][T];
  constexpr int b = hT.tb[C][T];
  if constexpr (hT.ts[C][T] > 0.f)
    acc = fmaf(wi[a], wj[b], acc);
  else
    acc = fmaf(-wi[a], wj[b], acc);
  if constexpr (T + 1 < 6) return dterms<C, T + 1>(wi, wj, acc);
  return acc;
}

// compute c = 2U, 2U+1; split to bf16 hi/lo; store immediately (small live set)
template <int U, int UEND>
__device__ __forceinline__ void dBf16(char* smc, uint32_t rowOff,
                                      const float (&wi)[21], const float (&wj)[21]) {
  float d0 = dterms<2 * U, 0>(wi, wj, 0.0f);
  float d1 = dterms<2 * U + 1, 0>(wi, wj, 0.0f);
  uint32_t hw = bf16x2pack(d0, d1);
  float r0 = d0 - __uint_as_float(hw << 16);
  float r1 = d1 - __uint_as_float(hw & 0xffff0000u);
  uint32_t lw = bf16x2pack(r0, r1);
  *(uint32_t*)(smc + rowOff + 4 * U) = hw;
  *(uint32_t*)(smc + A_BYTES + rowOff + 4 * U) = lw;
  if constexpr (U + 1 < UEND) dBf16<U + 1, UEND>(smc, rowOff, wi, wj);
}

template <int C, int CEND>
__device__ __forceinline__ void dF32(float* ds, int pair,
                                     const float (&wi)[21], const float (&wj)[21]) {
  ds[(C - 32) * 256 + pair] = dterms<C, 0>(wi, wj, 0.0f);
  if constexpr (C + 1 < CEND) dF32<C + 1, CEND>(ds, pair, wi, wj);
}

// ======================= kernel 2: hybrid HMMA + fp32-tail GEMM =================
// grid 148 x 512. c[0,32): bf16-split HMMA (60 MMA/warp/n, tensor pipe).
// c[32,35): exact fp32 FMA into the same fragments (fma pipe, mostly idle).
// A + Ds32 warp-private (syncwarp); B/Pf/Ws double-buffered -> 1 barrier per n.
__global__ void __launch_bounds__(512, 1)
k_main(const float* __restrict__ omega, const float* __restrict__ Phi, int n,
       int chunk) {
  extern __shared__ char smc[];
  const int tid  = threadIdx.x;
  const int w    = tid >> 5;
  const int lane = tid & 31;
  const uint32_t smb = cvta_smem(smc);

  // zero all tiles once (k/n padding persists as zeros)
  for (int i = tid; i < SMEM_MAIN / 4; i += 512) ((uint32_t*)smc)[i] = 0u;

  int n0 = blockIdx.x * chunk;
  int n1 = n0 + chunk;
  if (n1 > n) n1 = n;

  if (n0 >= n1) {
    __syncthreads();
    for (int i = tid; i < 256 * 80; i += 512) g_part[blockIdx.x][i] = 0.f;
    return;
  }

  const int myPair = w * 16 + (lane & 15);
  const int pi = dT.p2i[myPair];
  const int pj = dT.p2j[myPair];
  const int halfHi = lane >> 4;
  const int g = lane >> 2;
  const int t = lane & 3;

  // staging map: idx = tid + j*512 -> (k, c). c<32 -> bf16 B tile byte offset;
  // c>=32 -> fp32 Pf float index.
  uint32_t bOff[6];
  bool bAct[6], bIsB[6];
#pragma unroll
  for (int j = 0; j < 6; j++) {
    int idx = tid + j * 512;
    bAct[j] = idx < 2695;
    int k = idx / 35;
    int c = idx - k * 35;
    bIsB[j] = c < 32;
    bOff[j] = bIsB[j] ? (uint32_t)(k * AROW + c * 2)
                      : (uint32_t)((c - 32) * 80 + k);
  }

  // ldmatrix lane addresses
  const uint32_t aRow  = (uint32_t)(w * 16 + ((lane >> 3) & 1) * 8 + (lane & 7));
  const uint32_t aAddr = smb + aRow * AROW + (uint32_t)(lane >> 4) * 16;
  const uint32_t bRow  = (uint32_t)(((lane >> 4) & 1) * 8 + (lane & 7));
  const uint32_t bAddr0 = smb + OFF_B + bRow * AROW +
                          (uint32_t)((lane >> 3) & 1) * 16;

  float acc[10][4];
#pragma unroll
  for (int a = 0; a < 10; a++)
#pragma unroll
    for (int b = 0; b < 4; b++) acc[a][b] = 0.f;

  // prefetch first n
  float rO = 0.f, rP[6], rWn = 0.f;
#pragma unroll
  for (int j = 0; j < 6; j++) rP[j] = 0.f;
  {
    const float* og = omega + (size_t)n0 * 441;
    if (tid < 441) rO = og[tid];
    const float* pg = Phi + (size_t)n0 * 2695;
#pragma unroll
    for (int j = 0; j < 6; j++)
      if (bAct[j]) rP[j] = pg[tid + j * 512];
    rWn = g_w[n0];
  }
  __syncthreads();  // zero-init visible

  int buf = 0;
#pragma unroll 1
  for (int nn = n0; nn < n1; nn++) {
    char*  bb = smc + OFF_B + (buf ? 2 * B_BYTES : 0);
    float* pf = (float*)(smc + OFF_PF) + (buf ? 240 : 0);
    float* Ws = (float*)(smc + OFF_WS) + (buf ? 448 : 0);
    float* ds = (float*)(smc + OFF_DS);

    // ---- stage Ws + B[buf] + Pf[buf] from prefetched regs ----
    if (tid < 441) Ws[tid] = rO;
    {
      const float wn = rWn;
#pragma unroll
      for (int j = 0; j < 6; j++) {
        if (bAct[j]) {
          float v = rP[j] * wn;
          if (bIsB[j]) {
            __nv_bfloat16 bh = __float2bfloat16(v);
            float res = v - __bfloat162float(bh);
            __nv_bfloat16 bl = __float2bfloat16(res);
            *(__nv_bfloat16*)(bb + bOff[j]) = bh;
            *(__nv_bfloat16*)(bb + B_BYTES + bOff[j]) = bl;
          } else {
            pf[bOff[j]] = v;
          }
        }
      }
    }

    // ---- prefetch next n ----
    {
      int nx = (nn + 1 < n1) ? nn + 1 : nn;
      const float* og = omega + (size_t)nx * 441;
      if (tid < 441) rO = og[tid];
      const float* pg = Phi + (size_t)nx * 2695;
#pragma unroll
      for (int j = 0; j < 6; j++)
        if (bAct[j]) rP[j] = pg[tid + j * 512];
      rWn = g_w[nx];
    }
    __syncthreads();   // the ONE block barrier: Ws/B/Pf[buf] visible

    // ---- D-phase: warp-private A (bf16 hi/lo, c<32) + Ds32 (fp32, c>=32) ----
    __syncwarp();      // prior GEMM's reads done before overwriting A/Ds32
    {
      float wi[21], wj[21];
      const float* Wi = &Ws[pi * 21];
      const float* Wj = &Ws[pj * 21];
#pragma unroll
      for (int a = 0; a < 21; a++) { wi[a] = Wi[a]; wj[a] = Wj[a]; }
      const uint32_t rowOff = (uint32_t)(myPair * AROW);
      if (!halfHi) {
        dBf16<0, 9>(smc, rowOff, wi, wj);       // c 0..17
      } else {
        dBf16<9, 16>(smc, rowOff, wi, wj);      // c 18..31
        dF32<32, 35>(ds, myPair, wi, wj);       // c 32..34 exact fp32
      }
    }
    __syncwarp();      // own A/Ds32 writes visible to own warp

    // ---- GEMM tensor part: 2 K-chunks x 5 tp x {hh, hl, lh} ----
    const uint32_t bAddr = bAddr0 + (buf ? (uint32_t)(2 * B_BYTES) : 0u);
#pragma unroll
    for (int ks = 0; ks < 2; ks++) {
      uint32_t ah[4], al[4];
      LDSM_X4(ah[0], ah[1], ah[2], ah[3], aAddr + ks * 32);
      LDSM_X4(al[0], al[1], al[2], al[3], aAddr + A_BYTES + ks * 32);
#pragma unroll
      for (int tp = 0; tp < 5; tp++) {
        uint32_t bh[4], bl[4];
        uint32_t ba = bAddr + (uint32_t)(tp * 16 * AROW) + ks * 32;
        LDSM_X4(bh[0], bh[1], bh[2], bh[3], ba);
        LDSM_X4(bl[0], bl[1], bl[2], bl[3], ba + B_BYTES);
        MMA_BF16(acc[2 * tp],     ah, bh[0], bh[1]);
        MMA_BF16(acc[2 * tp],     ah, bl[0], bl[1]);
        MMA_BF16(acc[2 * tp],     al, bh[0], bh[1]);
        MMA_BF16(acc[2 * tp + 1], ah, bh[2], bh[3]);
        MMA_BF16(acc[2 * tp + 1], ah, bl[2], bl[3]);
        MMA_BF16(acc[2 * tp + 1], al, bh[2], bh[3]);
      }
    }

    // ---- GEMM fp32 tail: c 32..34 straight into the same fragments ----
    {
      const int base = w * 16 + g;
#pragma unroll
      for (int c2 = 0; c2 < 3; c2++) {
        float dr0 = ds[c2 * 256 + base];
        float dr1 = ds[c2 * 256 + base + 8];
        const float* prow = &pf[c2 * 80 + 2 * t];
#pragma unroll
        for (int nt = 0; nt < 10; nt++) {
          float2 pv = *(const float2*)&prow[nt * 8];
          acc[nt][0] = fmaf(dr0, pv.x, acc[nt][0]);
          acc[nt][1] = fmaf(dr0, pv.y, acc[nt][1]);
          acc[nt][2] = fmaf(dr1, pv.x, acc[nt][2]);
          acc[nt][3] = fmaf(dr1, pv.y, acc[nt][3]);
        }
      }
    }
    buf ^= 1;
  }

  // epilogue: spill register accumulators to g_part
  {
    const int r0 = w * 16 + g, r1 = r0 + 8;
    float* dst = g_part[blockIdx.x];
#pragma unroll
    for (int nt = 0; nt < 10; nt++) {
      int col = nt * 8 + 2 * t;
      *(float2*)&dst[r0 * 80 + col] = make_float2(acc[nt][0], acc[nt][1]);
      *(float2*)&dst[r1 * 80 + col] = make_float2(acc[nt][2], acc[nt][3]);
    }
  }
}

// ======================= kernel 3a: reduce partials (8-way n-chunk) =============
__global__ void __launch_bounds__(128, 8)
k_reduceS() {
  const int t = blockIdx.x * 128 + threadIdx.x;
  if (t >= NPAIR * 20) return;
  const int p = t / 20;
  const int q = t - p * 20;
  const int y = blockIdx.y;
  const int b0  = (y < 4) ? y * 19 : 76 + (y - 4) * 18;
  const int cnt = (y < 4) ? 19 : 18;
  float4 s = make_float4(0.f, 0.f, 0.f, 0.f);
#pragma unroll 4
  for (int b = 0; b < cnt; b++) {
    float4 v = *(const float4*)&g_part[b0 + b][p * 80 + q * 4];
    s.x += v.x; s.y += v.y; s.z += v.z; s.w += v.w;
  }
  *(float4*)&g_S8[y][p * 80 + q * 4] = s;
}

// ======================= kernel 3b: emit Y + final S ============================
__global__ void k_emitY(float* __restrict__ out, int writeY) {
  int idx = blockIdx.x * blockDim.x + threadIdx.x;
  if (idx >= 441 * 77) return;
  const float inv = g_invsum;
  int i = idx / 1617;
  int rem = idx - i * 1617;
  int j = rem / 77;
  int k = rem - j * 77;
  int lo = i < j ? i : j;
  int hi = i < j ? j : i;
  int p = lo * 21 - lo * (lo - 1) / 2 + (hi - lo);
  int o = p * 80 + k;
  float s = ((g_S8[0][o] + g_S8[1][o]) + (g_S8[2][o] + g_S8[3][o])) +
            ((g_S8[4][o] + g_S8[5][o]) + (g_S8[6][o] + g_S8[7][o]));
  s *= inv;
  if (writeY) out[idx] = (j >= i) ? s : -s;
  if (i <= j) g_S[p * 77 + k] = s;
}

// ======================= kernel 4: build M = S^T diag(m) S ======================
__global__ void __launch_bounds__(128, 1)
k_buildM(float* __restrict__ out, int oM) {
  __shared__ float cs[NPAIR];
  const int k = blockIdx.x;
  const int tid = threadIdx.x;
  for (int p = tid; p < NPAIR; p += 128) {
    float wgt = (dT.p2i[p] == dT.p2j[p]) ? 1.f : 2.f;
    cs[p] = wgt * g_S[p * 77 + k];
  }
  __syncthreads();
  if (tid < 77) {
    float a0 = 0.f, a1 = 0.f, a2 = 0.f, a3 = 0.f;
    int p = 0;
#pragma unroll 4
    for (; p + 4 <= NPAIR; p += 4) {
      a0 = fmaf(cs[p],     g_S[p * 77 + tid],       a0);
      a1 = fmaf(cs[p + 1], g_S[(p + 1) * 77 + tid], a1);
      a2 = fmaf(cs[p + 2], g_S[(p + 2) * 77 + tid], a2);
      a3 = fmaf(cs[p + 3], g_S[(p + 3) * 77 + tid], a3);
    }
    for (; p < NPAIR; p++) a0 = fmaf(cs[p], g_S[p * 77 + tid], a0);
    float v = (a0 + a1) + (a2 + a3);
    out[oM + k * 77 + tid] = v;
    g_A[k * 77 + tid] = v;
  }
}

// ======================= kernel 5: Householder tridiagonalization ===============
__device__ __forceinline__ float blockReduce256(float v, volatile float* red,
                                                int tid) {
  __syncthreads();
#pragma unroll
  for (int o = 16; o; o >>= 1) v += __shfl_down_sync(0xffffffffu, v, o);
  if ((tid & 31) == 0) red[tid >> 5] = v;
  __syncthreads();
  if (tid < 8) {
    float r = red[tid];
#pragma unroll
    for (int o = 4; o; o >>= 1) r += __shfl_down_sync(0xffu, r, o);
    if (tid == 0) red[0] = r;
  }
  __syncthreads();
  return red[0];
}

__global__ void __launch_bounds__(256, 1) k_tridiag() {
  __shared__ float A[NK * TLD];
  __shared__ float us[80], ps[80], pp[80];
  __shared__ float red[8];
  __shared__ float dd[NK], ee[NK];
  __shared__ float scA, scTb;
  __shared__ int   skip;
  const int tid  = threadIdx.x;
  const int lane = tid & 31;
  const int warp = tid >> 5;
  const int rrow = tid >> 1;
  const int rq   = tid & 1;

  for (int idx = tid; idx < NK * NK; idx += 256) {
    int r = idx / NK, c = idx - r * NK;
    A[r * TLD + c] = g_A[idx];
  }
  __syncthreads();

#pragma unroll 1
  for (int k = 0; k < 75; k++) {
    const int m = 76 - k;
    float v = 0.f;
    if (tid < m) v = A[(k + 1 + tid) * TLD + k];
    float sigma = blockReduce256(v * v, red, tid);
    if (tid == 0) {
      dd[k] = A[k * TLD + k];
      if (sigma < 1e-30f) {
        ee[k] = 0.f;
        skip = 1;
      } else {
        float v0 = A[(k + 1) * TLD + k];
        float alpha = -copysignf(sqrtf(sigma), v0);
        ee[k] = alpha;
        scA = alpha;
        float beta = 2.f * (sigma - v0 * alpha);
        scTb = 2.f / beta;
        skip = 0;
      }
    }
    __syncthreads();
    if (skip) continue;

    if (tid < m) us[tid] = (tid == 0) ? v - scA : v;
    __syncthreads();

    {
      float a0 = 0.f, a1 = 0.f, a2 = 0.f, a3 = 0.f;
      if (rrow < m) {
        const float* row = &A[(k + 1 + rrow) * TLD + (k + 1)];
        int j = rq;
        for (; j + 6 < m; j += 8) {
          a0 = fmaf(row[j],     us[j],     a0);
          a1 = fmaf(row[j + 2], us[j + 2], a1);
          a2 = fmaf(row[j + 4], us[j + 4], a2);
          a3 = fmaf(row[j + 6], us[j + 6], a3);
        }
        for (; j < m; j += 2) a0 = fmaf(row[j], us[j], a0);
      }
      float s = (a0 + a1) + (a2 + a3);
      s += __shfl_xor_sync(0xffffffffu, s, 1);
      if (rrow < m && rq == 0) pp[rrow] = s * scTb;
    }
    __syncthreads();
    float upT = blockReduce256((tid < m) ? pp[tid] * us[tid] : 0.f, red, tid);
    if (tid < m) ps[tid] = pp[tid] - (upT * scTb * 0.5f) * us[tid];
    __syncthreads();

    for (int i = warp; i < m; i += 8) {
      const float ui = us[i], pi_ = ps[i];
      float* rowA = &A[(k + 1 + i) * TLD + (k + 1)];
      for (int j = lane; j < m; j += 32)
        rowA[j] -= ui * ps[j] + pi_ * us[j];
    }
    __syncthreads();
  }

  if (tid == 0) {
    dd[75] = A[75 * TLD + 75];
    ee[75] = A[76 * TLD + 75];
    dd[76] = A[76 * TLD + 76];
    ee[76] = 0.f;
  }
  __syncthreads();
  if (tid < NK) {
    g_d[tid] = dd[tid];
    g_e[tid] = ee[tid];
  }
}

// ======================= kernel 6: Sturm multisection eigenvalues ===============
#define NPROBE 13
#define NROUND 10

__global__ void __launch_bounds__(1024, 1)
k_bisect(float* __restrict__ out, int oE) {
  __shared__ float d_s[NK], e2_s[NK];
  __shared__ float lo_s[NK], hi_s[NK];
  __shared__ float xs[NK * NPROBE];
  __shared__ int   cs[NK * NPROBE];
  __shared__ float gl_s, gh_s, piv_s;
  const int tid = threadIdx.x;
  const int g = tid / NPROBE;
  const int j = tid - g * NPROBE;
  const bool act = (g < NK);

  if (tid < NK) {
    d_s[tid] = g_d[tid];
    float e = g_e[tid];
    e2_s[tid] = e * e;
  }
  __syncthreads();

  if (tid == 0) {
    float gl = 3.4e38f, gh = -3.4e38f, me2 = 0.f;
    for (int i = 0; i < NK; i++) {
      float eprev = (i > 0) ? sqrtf(e2_s[i - 1]) : 0.f;
      float ecur  = (i < 76) ? sqrtf(e2_s[i]) : 0.f;
      float r = eprev + ecur;
      gl = fminf(gl, d_s[i] - r);
      gh = fmaxf(gh, d_s[i] + r);
      me2 = fmaxf(me2, e2_s[i]);
    }
    float wid = fmaxf(gh - gl, 1e-20f);
    gl_s = gl - 1e-3f * wid;
    gh_s = gh + 1e-3f * wid;
    piv_s = fmaxf(me2 * 1.2e-38f, 1e-37f);
  }
  __syncthreads();
  if (tid < NK) { lo_s[tid] = gl_s; hi_s[tid] = gh_s; }
  __syncthreads();

  const float pivmin = piv_s;
  const float cj = (float)(j + 1) / (float)(NPROBE + 1);

#pragma unroll 1
  for (int r = 0; r < NROUND; r++) {
    if (act) {
      float lo = lo_s[g], hi = hi_s[g];
      float x = lo + (hi - lo) * cj;
      xs[tid] = x;
      float q = d_s[0] - x;
      int cnt = (q < 0.f);
#pragma unroll 4
      for (int i = 1; i < NK; i++) {
        float aq = fabsf(q);
        if (aq < pivmin) q = -pivmin;
        q = d_s[i] - x - __fdividef(e2_s[i - 1], q);
        cnt += (q < 0.f);
      }
      cs[tid] = cnt;
    }
    __syncthreads();
    if (act && j == 0) {
      float lo = lo_s[g], hi = hi_s[g];
      for (int jj = 0; jj < NPROBE; jj++) {
        int c = cs[g * NPROBE + jj];
        float x = xs[g * NPROBE + jj];
        if (c <= g) lo = x;
        else { hi = x; break; }
      }
      lo_s[g] = lo;
      hi_s[g] = hi;
    }
    __syncthreads();
  }

  if (act && j == 0) out[oE + (76 - g)] = 0.5f * (lo_s[g] + hi_s[g]);
}

// ======================= launch =================================================
extern "C" void kernel_launch(void* const* d_in, const int* in_sizes, int n_in,
                              void* d_out, int out_size) {
  const float* omega  = (const float*)d_in[0];
  const float* Phi    = (const float*)d_in[1];
  const float* metric = (const float*)d_in[2];
  int n = in_sizes[2] / 49;
  if (n > NMAX) n = NMAX;

  float* out = (float*)d_out;
  int oE = out_size - 77;
  int oM = oE - 77 * 77;
  int writeY = (out_size >= 33957 + 77 * 77 + 77) ? 1 : 0;

  int nb = (n + 255) / 256;
  k_vols<<<nb, 256>>>(metric, n);

  int chunk = (n + NGRID - 1) / NGRID;
  cudaFuncSetAttribute(k_main, cudaFuncAttributeMaxDynamicSharedMemorySize,
                       SMEM_MAIN);
  k_main<<<NGRID, 512, SMEM_MAIN>>>(omega, Phi, n, chunk);

  k_reduceS<<<dim3((NPAIR * 20 + 127) / 128, NRED), 128>>>();
  k_emitY<<<(441 * 77 + 255) / 256, 256>>>(out, writeY);

  k_buildM<<<77, 128>>>(out, oM);
  k_tridiag<<<1, 256>>>();
  k_bisect<<<1, 1024>>>(out, oE);
}

// round 13
// speedup vs baseline: 1.0558x; 1.0002x over previous
#include <cuda_runtime.h>
#include <cuda_bf16.h>
#include <math.h>
#include <stdint.h>

// ======================= compile-time structure constants =======================
struct Tables {
  signed char   ta[35][6];
  signed char   tb[35][6];
  float         ts[35][6];
  unsigned char p2i[256];
  unsigned char p2j[256];
};

constexpr Tables makeTables() {
  Tables T{};
  int c = 0;
  for (int x = 0; x < 7; x++)
    for (int y = x + 1; y < 7; y++)
      for (int z = y + 1; z < 7; z++) {
        int comp[4] = {0, 0, 0, 0};
        int m = 0;
        for (int e = 0; e < 7; e++)
          if (e != x && e != y && e != z) comp[m++] = e;
        int t = 0;
        for (int u = 0; u < 4; u++)
          for (int v = u + 1; v < 4; v++) {
            int a0 = comp[u], a1 = comp[v];
            int b0 = -1, b1 = -1;
            for (int e = 0; e < 4; e++) {
              if (e != u && e != v) { if (b0 < 0) b0 = comp[e]; else b1 = comp[e]; }
            }
            int perm[7] = {a0, a1, b0, b1, x, y, z};
            int inv = 0;
            for (int q = 0; q < 7; q++)
              for (int r = q + 1; r < 7; r++)
                if (perm[q] > perm[r]) inv++;
            T.ts[c][t] = (inv & 1) ? -1.0f : 1.0f;
            T.ta[c][t] = (signed char)(6 * a0 - a0 * (a0 - 1) / 2 + (a1 - a0 - 1));
            T.tb[c][t] = (signed char)(6 * b0 - b0 * (b0 - 1) / 2 + (b1 - b0 - 1));
            t++;
          }
        c++;
      }
  int p = 0;
  for (int i = 0; i < 21; i++)
    for (int j = i; j < 21; j++) {
      T.p2i[p] = (unsigned char)i;
      T.p2j[p] = (unsigned char)j;
      p++;
    }
  for (; p < 256; p++) { T.p2i[p] = 0; T.p2j[p] = 0; }
  return T;
}

constexpr Tables hT = makeTables();
__constant__ Tables dT = makeTables();

// ======================= device scratch =========================================
#define NMAX   4096
#define NGRID  148
#define NPAIR  231
#define NK     77
#define TLD    79
#define NRED   8

__device__ float g_w[NMAX];
__device__ float g_psum[64];
__device__ float g_invsum;
__device__ unsigned int g_cnt = 0;
__device__ float g_part[NGRID][256 * 80];
__device__ float g_S8[NRED][NPAIR * 80];
__device__ float g_S[NPAIR * NK];
__device__ float g_A[NK * NK];

// ======================= helpers ================================================
__device__ __forceinline__ uint32_t cvta_smem(const void* p) {
  uint32_t a;
  asm("{ .reg .u64 t; cvta.to.shared.u64 t, %1; cvt.u32.u64 %0, t; }"
      : "=r"(a) : "l"(p));
  return a;
}

__device__ __forceinline__ uint32_t bf16x2pack(float lo, float hi) {
  uint32_t r;
  asm("cvt.rn.bf16x2.f32 %0, %1, %2;" : "=r"(r) : "f"(hi), "f"(lo));
  return r;
}

#define LDSM_X4(r0, r1, r2, r3, addr) \
  asm volatile("ldmatrix.sync.aligned.m8n8.x4.shared.b16 {%0,%1,%2,%3}, [%4];" \
               : "=r"(r0), "=r"(r1), "=r"(r2), "=r"(r3) : "r"(addr))

#define MMA_BF16(c, a, b0_, b1_) \
  asm volatile("mma.sync.aligned.m16n8k16.row.col.f32.bf16.bf16.f32 " \
               "{%0,%1,%2,%3}, {%4,%5,%6,%7}, {%8,%9}, {%0,%1,%2,%3};" \
               : "+f"((c)[0]), "+f"((c)[1]), "+f"((c)[2]), "+f"((c)[3]) \
               : "r"((a)[0]), "r"((a)[1]), "r"((a)[2]), "r"((a)[3]), \
                 "r"(b0_), "r"(b1_))

// smem layout bytes (k_main) — unchanged from R12
#define AROW      80
#define A_BYTES   (256 * AROW)
#define B_BYTES   (80 * AROW)
#define OFF_B     (2 * A_BYTES)
#define OFF_PF    (OFF_B + 4 * B_BYTES)
#define OFF_DS    (OFF_PF + 2 * 240 * 4)
#define OFF_WS    (OFF_DS + 3 * 256 * 4)
#define SMEM_MAIN (OFF_WS + 2 * 448 * 4)

// ======================= kernel 0: no-op (profiler slot alignment) ==============
__global__ void k_nop() {}

// ======================= kernel 1: volumes + fused normalization sum ============
__global__ void __launch_bounds__(256, 1)
k_vols(const float* __restrict__ metric, int n) {
  __shared__ float red[256];
  __shared__ bool amLast;
  const int tid = threadIdx.x;
  const int idx = blockIdx.x * 256 + tid;
  float vol = 0.f;
  if (idx < n) {
    float a[7][7];
#pragma unroll
    for (int r = 0; r < 7; r++)
#pragma unroll
      for (int cc = 0; cc < 7; cc++) a[r][cc] = metric[idx * 49 + r * 7 + cc];
    float det = 1.f;
#pragma unroll
    for (int k = 0; k < 7; k++) {
      float mx = fabsf(a[k][k]);
      int piv = k;
#pragma unroll
      for (int r = k + 1; r < 7; r++) {
        float v = fabsf(a[r][k]);
        if (v > mx) { mx = v; piv = r; }
      }
#pragma unroll
      for (int r = k + 1; r < 7; r++) {
        if (piv == r) {
          det = -det;
#pragma unroll
          for (int cc = k; cc < 7; cc++) {
            float t = a[k][cc]; a[k][cc] = a[r][cc]; a[r][cc] = t;
          }
        }
      }
      float akk = a[k][k];
      det *= akk;
      float inv = (akk != 0.f) ? 1.f / akk : 0.f;
#pragma unroll
      for (int r = k + 1; r < 7; r++) {
        float f = a[r][k] * inv;
#pragma unroll
        for (int cc = k + 1; cc < 7; cc++) a[r][cc] = fmaf(-f, a[k][cc], a[r][cc]);
      }
    }
    vol = sqrtf(fabsf(det));
    g_w[idx] = vol;
  }
  red[tid] = vol;
  __syncthreads();
#pragma unroll
  for (int s = 128; s > 0; s >>= 1) {
    if (tid < s) red[tid] += red[tid + s];
    __syncthreads();
  }
  if (tid == 0) {
    g_psum[blockIdx.x] = red[0];
    __threadfence();
    unsigned int done = atomicAdd(&g_cnt, 1u);
    amLast = (done == gridDim.x - 1);
  }
  __syncthreads();
  if (amLast && tid == 0) {
    g_cnt = 0;
    float s = 0.f;
    for (unsigned int i = 0; i < gridDim.x; i++) s += g_psum[i];
    g_invsum = 1.f / s;
  }
}

// ======================= D-compute: fully unrolled ==============================
template <int C, int T>
__device__ __forceinline__ float dterms(const float (&wi)[21], const float (&wj)[21],
                                        float acc) {
  constexpr int a = hT.ta[C][T];
  constexpr int b = hT.tb[C][T];
  if constexpr (hT.ts[C][T] > 0.f)
    acc = fmaf(wi[a], wj[b], acc);
  else
    acc = fmaf(-wi[a], wj[b], acc);
  if constexpr (T + 1 < 6) return dterms<C, T + 1>(wi, wj, acc);
  return acc;
}

template <int U, int UEND>
__device__ __forceinline__ void dBf16(char* smc, uint32_t rowOff,
                                      const float (&wi)[21], const float (&wj)[21]) {
  float d0 = dterms<2 * U, 0>(wi, wj, 0.0f);
  float d1 = dterms<2 * U + 1, 0>(wi, wj, 0.0f);
  uint32_t hw = bf16x2pack(d0, d1);
  float r0 = d0 - __uint_as_float(hw << 16);
  float r1 = d1 - __uint_as_float(hw & 0xffff0000u);
  uint32_t lw = bf16x2pack(r0, r1);
  *(uint32_t*)(smc + rowOff + 4 * U) = hw;
  *(uint32_t*)(smc + A_BYTES + rowOff + 4 * U) = lw;
  if constexpr (U + 1 < UEND) dBf16<U + 1, UEND>(smc, rowOff, wi, wj);
}

template <int C, int CEND>
__device__ __forceinline__ void dF32(float* ds, int pair,
                                     const float (&wi)[21], const float (&wj)[21]) {
  ds[(C - 32) * 256 + pair] = dterms<C, 0>(wi, wj, 0.0f);
  if constexpr (C + 1 < CEND) dF32<C + 1, CEND>(ds, pair, wi, wj);
}

// ======================= kernel 2: hybrid HMMA + fp32-tail GEMM (R12 verbatim) ==
__global__ void __launch_bounds__(512, 1)
k_main(const float* __restrict__ omega, const float* __restrict__ Phi, int n,
       int chunk) {
  extern __shared__ char smc[];
  const int tid  = threadIdx.x;
  const int w    = tid >> 5;
  const int lane = tid & 31;
  const uint32_t smb = cvta_smem(smc);

  for (int i = tid; i < SMEM_MAIN / 4; i += 512) ((uint32_t*)smc)[i] = 0u;

  int n0 = blockIdx.x * chunk;
  int n1 = n0 + chunk;
  if (n1 > n) n1 = n;

  if (n0 >= n1) {
    __syncthreads();
    for (int i = tid; i < 256 * 80; i += 512) g_part[blockIdx.x][i] = 0.f;
    return;
  }

  const int myPair = w * 16 + (lane & 15);
  const int pi = dT.p2i[myPair];
  const int pj = dT.p2j[myPair];
  const int halfHi = lane >> 4;
  const int g = lane >> 2;
  const int t = lane & 3;

  uint32_t bOff[6];
  bool bAct[6], bIsB[6];
#pragma unroll
  for (int j = 0; j < 6; j++) {
    int idx = tid + j * 512;
    bAct[j] = idx < 2695;
    int k = idx / 35;
    int c = idx - k * 35;
    bIsB[j] = c < 32;
    bOff[j] = bIsB[j] ? (uint32_t)(k * AROW + c * 2)
                      : (uint32_t)((c - 32) * 80 + k);
  }

  const uint32_t aRow  = (uint32_t)(w * 16 + ((lane >> 3) & 1) * 8 + (lane & 7));
  const uint32_t aAddr = smb + aRow * AROW + (uint32_t)(lane >> 4) * 16;
  const uint32_t bRow  = (uint32_t)(((lane >> 4) & 1) * 8 + (lane & 7));
  const uint32_t bAddr0 = smb + OFF_B + bRow * AROW +
                          (uint32_t)((lane >> 3) & 1) * 16;

  float acc[10][4];
#pragma unroll
  for (int a = 0; a < 10; a++)
#pragma unroll
    for (int b = 0; b < 4; b++) acc[a][b] = 0.f;

  float rO = 0.f, rP[6], rWn = 0.f;
#pragma unroll
  for (int j = 0; j < 6; j++) rP[j] = 0.f;
  {
    const float* og = omega + (size_t)n0 * 441;
    if (tid < 441) rO = og[tid];
    const float* pg = Phi + (size_t)n0 * 2695;
#pragma unroll
    for (int j = 0; j < 6; j++)
      if (bAct[j]) rP[j] = pg[tid + j * 512];
    rWn = g_w[n0];
  }
  __syncthreads();

  int buf = 0;
#pragma unroll 1
  for (int nn = n0; nn < n1; nn++) {
    char*  bb = smc + OFF_B + (buf ? 2 * B_BYTES : 0);
    float* pf = (float*)(smc + OFF_PF) + (buf ? 240 : 0);
    float* Ws = (float*)(smc + OFF_WS) + (buf ? 448 : 0);
    float* ds = (float*)(smc + OFF_DS);

    if (tid < 441) Ws[tid] = rO;
    {
      const float wn = rWn;
#pragma unroll
      for (int j = 0; j < 6; j++) {
        if (bAct[j]) {
          float v = rP[j] * wn;
          if (bIsB[j]) {
            __nv_bfloat16 bh = __float2bfloat16(v);
            float res = v - __bfloat162float(bh);
            __nv_bfloat16 bl = __float2bfloat16(res);
            *(__nv_bfloat16*)(bb + bOff[j]) = bh;
            *(__nv_bfloat16*)(bb + B_BYTES + bOff[j]) = bl;
          } else {
            pf[bOff[j]] = v;
          }
        }
      }
    }

    {
      int nx = (nn + 1 < n1) ? nn + 1 : nn;
      const float* og = omega + (size_t)nx * 441;
      if (tid < 441) rO = og[tid];
      const float* pg = Phi + (size_t)nx * 2695;
#pragma unroll
      for (int j = 0; j < 6; j++)
        if (bAct[j]) rP[j] = pg[tid + j * 512];
      rWn = g_w[nx];
    }
    __syncthreads();

    __syncwarp();
    {
      float wi[21], wj[21];
      const float* Wi = &Ws[pi * 21];
      const float* Wj = &Ws[pj * 21];
#pragma unroll
      for (int a = 0; a < 21; a++) { wi[a] = Wi[a]; wj[a] = Wj[a]; }
      const uint32_t rowOff = (uint32_t)(myPair * AROW);
      if (!halfHi) {
        dBf16<0, 9>(smc, rowOff, wi, wj);
      } else {
        dBf16<9, 16>(smc, rowOff, wi, wj);
        dF32<32, 35>(ds, myPair, wi, wj);
      }
    }
    __syncwarp();

    const uint32_t bAddr = bAddr0 + (buf ? (uint32_t)(2 * B_BYTES) : 0u);
#pragma unroll
    for (int ks = 0; ks < 2; ks++) {
      uint32_t ah[4], al[4];
      LDSM_X4(ah[0], ah[1], ah[2], ah[3], aAddr + ks * 32);
      LDSM_X4(al[0], al[1], al[2], al[3], aAddr + A_BYTES + ks * 32);
#pragma unroll
      for (int tp = 0; tp < 5; tp++) {
        uint32_t bh[4], bl[4];
        uint32_t ba = bAddr + (uint32_t)(tp * 16 * AROW) + ks * 32;
        LDSM_X4(bh[0], bh[1], bh[2], bh[3], ba);
        LDSM_X4(bl[0], bl[1], bl[2], bl[3], ba + B_BYTES);
        MMA_BF16(acc[2 * tp],     ah, bh[0], bh[1]);
        MMA_BF16(acc[2 * tp],     ah, bl[0], bl[1]);
        MMA_BF16(acc[2 * tp],     al, bh[0], bh[1]);
        MMA_BF16(acc[2 * tp + 1], ah, bh[2], bh[3]);
        MMA_BF16(acc[2 * tp + 1], ah, bl[2], bl[3]);
        MMA_BF16(acc[2 * tp + 1], al, bh[2], bh[3]);
      }
    }

    {
      const int base = w * 16 + g;
#pragma unroll
      for (int c2 = 0; c2 < 3; c2++) {
        float dr0 = ds[c2 * 256 + base];
        float dr1 = ds[c2 * 256 + base + 8];
        const float* prow = &pf[c2 * 80 + 2 * t];
#pragma unroll
        for (int nt = 0; nt < 10; nt++) {
          float2 pv = *(const float2*)&prow[nt * 8];
          acc[nt][0] = fmaf(dr0, pv.x, acc[nt][0]);
          acc[nt][1] = fmaf(dr0, pv.y, acc[nt][1]);
          acc[nt][2] = fmaf(dr1, pv.x, acc[nt][2]);
          acc[nt][3] = fmaf(dr1, pv.y, acc[nt][3]);
        }
      }
    }
    buf ^= 1;
  }

  {
    const int r0 = w * 16 + g, r1 = r0 + 8;
    float* dst = g_part[blockIdx.x];
#pragma unroll
    for (int nt = 0; nt < 10; nt++) {
      int col = nt * 8 + 2 * t;
      *(float2*)&dst[r0 * 80 + col] = make_float2(acc[nt][0], acc[nt][1]);
      *(float2*)&dst[r1 * 80 + col] = make_float2(acc[nt][2], acc[nt][3]);
    }
  }
}

// ======================= kernel 3a: reduce partials (8-way n-chunk) =============
__global__ void __launch_bounds__(128, 8)
k_reduceS() {
  const int t = blockIdx.x * 128 + threadIdx.x;
  if (t >= NPAIR * 20) return;
  const int p = t / 20;
  const int q = t - p * 20;
  const int y = blockIdx.y;
  const int b0  = (y < 4) ? y * 19 : 76 + (y - 4) * 18;
  const int cnt = (y < 4) ? 19 : 18;
  float4 s = make_float4(0.f, 0.f, 0.f, 0.f);
#pragma unroll 4
  for (int b = 0; b < cnt; b++) {
    float4 v = *(const float4*)&g_part[b0 + b][p * 80 + q * 4];
    s.x += v.x; s.y += v.y; s.z += v.z; s.w += v.w;
  }
  *(float4*)&g_S8[y][p * 80 + q * 4] = s;
}

// ======================= kernel 3b: emit Y + final S ============================
__global__ void k_emitY(float* __restrict__ out, int writeY) {
  int idx = blockIdx.x * blockDim.x + threadIdx.x;
  if (idx >= 441 * 77) return;
  const float inv = g_invsum;
  int i = idx / 1617;
  int rem = idx - i * 1617;
  int j = rem / 77;
  int k = rem - j * 77;
  int lo = i < j ? i : j;
  int hi = i < j ? j : i;
  int p = lo * 21 - lo * (lo - 1) / 2 + (hi - lo);
  int o = p * 80 + k;
  float s = ((g_S8[0][o] + g_S8[1][o]) + (g_S8[2][o] + g_S8[3][o])) +
            ((g_S8[4][o] + g_S8[5][o]) + (g_S8[6][o] + g_S8[7][o]));
  s *= inv;
  if (writeY) out[idx] = (j >= i) ? s : -s;
  if (i <= j) g_S[p * 77 + k] = s;
}

// ======================= kernel 4: build M = S^T diag(m) S ======================
__global__ void __launch_bounds__(128, 1)
k_buildM(float* __restrict__ out, int oM) {
  __shared__ float cs[NPAIR];
  const int k = blockIdx.x;
  const int tid = threadIdx.x;
  for (int p = tid; p < NPAIR; p += 128) {
    float wgt = (dT.p2i[p] == dT.p2j[p]) ? 1.f : 2.f;
    cs[p] = wgt * g_S[p * 77 + k];
  }
  __syncthreads();
  if (tid < 77) {
    float a0 = 0.f, a1 = 0.f, a2 = 0.f, a3 = 0.f;
    int p = 0;
#pragma unroll 4
    for (; p + 4 <= NPAIR; p += 4) {
      a0 = fmaf(cs[p],     g_S[p * 77 + tid],       a0);
      a1 = fmaf(cs[p + 1], g_S[(p + 1) * 77 + tid], a1);
      a2 = fmaf(cs[p + 2], g_S[(p + 2) * 77 + tid], a2);
      a3 = fmaf(cs[p + 3], g_S[(p + 3) * 77 + tid], a3);
    }
    for (; p < NPAIR; p++) a0 = fmaf(cs[p], g_S[p * 77 + tid], a0);
    float v = (a0 + a1) + (a2 + a3);
    out[oM + k * 77 + tid] = v;
    g_A[k * 77 + tid] = v;
  }
}

// ======================= kernel 5: fused tridiag (1024 thr) + Sturm bisect ======
__device__ __forceinline__ float blockReduce1024(float v, volatile float* red,
                                                 int tid) {
  __syncthreads();
#pragma unroll
  for (int o = 16; o; o >>= 1) v += __shfl_down_sync(0xffffffffu, v, o);
  if ((tid & 31) == 0) red[tid >> 5] = v;
  __syncthreads();
  if (tid < 32) {
    float r = red[tid];
#pragma unroll
    for (int o = 16; o; o >>= 1) r += __shfl_down_sync(0xffffffffu, r, o);
    if (tid == 0) red[0] = r;
  }
  __syncthreads();
  return red[0];
}

#define NPROBE 13
#define NROUND 10

__global__ void __launch_bounds__(1024, 1)
k_eig(float* __restrict__ out, int oE) {
  __shared__ float A[NK * TLD];
  __shared__ float us[80], ps[80], pp[80];
  __shared__ float red[32];
  __shared__ float dd[NK], ee[NK], e2s[NK];
  __shared__ float lo_s[NK], hi_s[NK];
  __shared__ float xs[NK * NPROBE];
  __shared__ int   cs[NK * NPROBE];
  __shared__ float scA, scTb, gl_s, gh_s, piv_s;
  __shared__ int   skip;
  const int tid  = threadIdx.x;
  const int lane = tid & 31;
  const int warp = tid >> 5;
  const int rrow = tid >> 2;   // matvec: 4 threads per row
  const int rq   = tid & 3;

  for (int idx = tid; idx < NK * NK; idx += 1024) {
    int r = idx / NK, c = idx - r * NK;
    A[r * TLD + c] = g_A[idx];
  }
  __syncthreads();

  // ---- Householder tridiagonalization, 32 warps ----
#pragma unroll 1
  for (int k = 0; k < 75; k++) {
    const int m = 76 - k;
    float v = 0.f;
    if (tid < m) v = A[(k + 1 + tid) * TLD + k];
    float sigma = blockReduce1024(v * v, red, tid);
    if (tid == 0) {
      dd[k] = A[k * TLD + k];
      if (sigma < 1e-30f) {
        ee[k] = 0.f;
        skip = 1;
      } else {
        float v0 = A[(k + 1) * TLD + k];
        float alpha = -copysignf(sqrtf(sigma), v0);
        ee[k] = alpha;
        scA = alpha;
        float beta = 2.f * (sigma - v0 * alpha);
        scTb = 2.f / beta;
        skip = 0;
      }
    }
    __syncthreads();
    if (skip) continue;

    if (tid < m) us[tid] = (tid == 0) ? v - scA : v;
    __syncthreads();

    // matvec p = scTb * A(sub) * u : 4 threads per row, quad-shuffle combine
    {
      float a0 = 0.f, a1 = 0.f, a2 = 0.f, a3 = 0.f;
      if (rrow < m) {
        const float* row = &A[(k + 1 + rrow) * TLD + (k + 1)];
        int j = rq;
        for (; j + 12 < m; j += 16) {
          a0 = fmaf(row[j],      us[j],      a0);
          a1 = fmaf(row[j + 4],  us[j + 4],  a1);
          a2 = fmaf(row[j + 8],  us[j + 8],  a2);
          a3 = fmaf(row[j + 12], us[j + 12], a3);
        }
        for (; j < m; j += 4) a0 = fmaf(row[j], us[j], a0);
      }
      float s = (a0 + a1) + (a2 + a3);
      s += __shfl_xor_sync(0xffffffffu, s, 1);
      s += __shfl_xor_sync(0xffffffffu, s, 2);
      if (rrow < m && rq == 0) pp[rrow] = s * scTb;
    }
    __syncthreads();   // pp visible before cross-thread read
    float upT = blockReduce1024((tid < m) ? pp[tid] * us[tid] : 0.f, red, tid);
    if (tid < m) ps[tid] = pp[tid] - (upT * scTb * 0.5f) * us[tid];
    __syncthreads();

    // rank-2 update: 32 warps, warp per row, lane per column
    for (int i = warp; i < m; i += 32) {
      const float ui = us[i], pi_ = ps[i];
      float* rowA = &A[(k + 1 + i) * TLD + (k + 1)];
      for (int j = lane; j < m; j += 32)
        rowA[j] -= ui * ps[j] + pi_ * us[j];
    }
    __syncthreads();
  }

  if (tid == 0) {
    dd[75] = A[75 * TLD + 75];
    ee[75] = A[76 * TLD + 75];
    dd[76] = A[76 * TLD + 76];
    ee[76] = 0.f;
  }
  __syncthreads();
  if (tid < NK) e2s[tid] = ee[tid] * ee[tid];
  __syncthreads();

  // ---- Sturm multisection eigenvalues (in the same launch) ----
  if (tid == 0) {
    float gl = 3.4e38f, gh = -3.4e38f, me2 = 0.f;
    for (int i = 0; i < NK; i++) {
      float eprev = (i > 0) ? sqrtf(e2s[i - 1]) : 0.f;
      float ecur  = (i < 76) ? sqrtf(e2s[i]) : 0.f;
      float r = eprev + ecur;
      gl = fminf(gl, dd[i] - r);
      gh = fmaxf(gh, dd[i] + r);
      me2 = fmaxf(me2, e2s[i]);
    }
    float wid = fmaxf(gh - gl, 1e-20f);
    gl_s = gl - 1e-3f * wid;
    gh_s = gh + 1e-3f * wid;
    piv_s = fmaxf(me2 * 1.2e-38f, 1e-37f);
  }
  __syncthreads();
  if (tid < NK) { lo_s[tid] = gl_s; hi_s[tid] = gh_s; }
  __syncthreads();

  const int gg = tid / NPROBE;
  const int jj = tid - gg * NPROBE;
  const bool act = (gg < NK);
  const float pivmin = piv_s;
  const float cj = (float)(jj + 1) / (float)(NPROBE + 1);

#pragma unroll 1
  for (int r = 0; r < NROUND; r++) {
    if (act) {
      float lo = lo_s[gg], hi = hi_s[gg];
      float x = lo + (hi - lo) * cj;
      xs[tid] = x;
      float q = dd[0] - x;
      int cnt = (q < 0.f);
#pragma unroll 4
      for (int i = 1; i < NK; i++) {
        float aq = fabsf(q);
        if (aq < pivmin) q = -pivmin;
        q = dd[i] - x - __fdividef(e2s[i - 1], q);
        cnt += (q < 0.f);
      }
      cs[tid] = cnt;
    }
    __syncthreads();
    if (act && jj == 0) {
      float lo = lo_s[gg], hi = hi_s[gg];
      for (int u = 0; u < NPROBE; u++) {
        int c = cs[gg * NPROBE + u];
        float x = xs[gg * NPROBE + u];
        if (c <= gg) lo = x;
        else { hi = x; break; }
      }
      lo_s[gg] = lo;
      hi_s[gg] = hi;
    }
    __syncthreads();
  }

  if (act && jj == 0) out[oE + (76 - gg)] = 0.5f * (lo_s[gg] + hi_s[gg]);
}

// ======================= launch =================================================
extern "C" void kernel_launch(void* const* d_in, const int* in_sizes, int n_in,
                              void* d_out, int out_size) {
  const float* omega  = (const float*)d_in[0];
  const float* Phi    = (const float*)d_in[1];
  const float* metric = (const float*)d_in[2];
  int n = in_sizes[2] / 49;
  if (n > NMAX) n = NMAX;

  float* out = (float*)d_out;
  int oE = out_size - 77;
  int oM = oE - 77 * 77;
  int writeY = (out_size >= 33957 + 77 * 77 + 77) ? 1 : 0;

  // two no-op launches so the ncu capture slot (#2/#3) lands on vols / k_main
  k_nop<<<1, 32>>>();
  k_nop<<<1, 32>>>();

  int nb = (n + 255) / 256;
  k_vols<<<nb, 256>>>(metric, n);

  int chunk = (n + NGRID - 1) / NGRID;
  cudaFuncSetAttribute(k_main, cudaFuncAttributeMaxDynamicSharedMemorySize,
                       SMEM_MAIN);
  k_main<<<NGRID, 512, SMEM_MAIN>>>(omega, Phi, n, chunk);

  k_reduceS<<<dim3((NPAIR * 20 + 127) / 128, NRED), 128>>>();
  k_emitY<<<(441 * 77 + 255) / 256, 256>>>(out, writeY);

  k_buildM<<<77, 128>>>(out, oM);
  k_eig<<<1, 1024>>>(out, oE);
}

// round 15
// speedup vs baseline: 1.1877x; 1.1249x over previous
#include <cuda_runtime.h>
#include <cuda_bf16.h>
#include <math.h>
#include <stdint.h>

// ======================= compile-time structure constants =======================
struct Tables {
  signed char   ta[35][6];
  signed char   tb[35][6];
  float         ts[35][6];
  unsigned char p2i[256];
  unsigned char p2j[256];
};

constexpr Tables makeTables() {
  Tables T{};
  int c = 0;
  for (int x = 0; x < 7; x++)
    for (int y = x + 1; y < 7; y++)
      for (int z = y + 1; z < 7; z++) {
        int comp[4] = {0, 0, 0, 0};
        int m = 0;
        for (int e = 0; e < 7; e++)
          if (e != x && e != y && e != z) comp[m++] = e;
        int t = 0;
        for (int u = 0; u < 4; u++)
          for (int v = u + 1; v < 4; v++) {
            int a0 = comp[u], a1 = comp[v];
            int b0 = -1, b1 = -1;
            for (int e = 0; e < 4; e++) {
              if (e != u && e != v) { if (b0 < 0) b0 = comp[e]; else b1 = comp[e]; }
            }
            int perm[7] = {a0, a1, b0, b1, x, y, z};
            int inv = 0;
            for (int q = 0; q < 7; q++)
              for (int r = q + 1; r < 7; r++)
                if (perm[q] > perm[r]) inv++;
            T.ts[c][t] = (inv & 1) ? -1.0f : 1.0f;
            T.ta[c][t] = (signed char)(6 * a0 - a0 * (a0 - 1) / 2 + (a1 - a0 - 1));
            T.tb[c][t] = (signed char)(6 * b0 - b0 * (b0 - 1) / 2 + (b1 - b0 - 1));
            t++;
          }
        c++;
      }
  int p = 0;
  for (int i = 0; i < 21; i++)
    for (int j = i; j < 21; j++) {
      T.p2i[p] = (unsigned char)i;
      T.p2j[p] = (unsigned char)j;
      p++;
    }
  for (; p < 256; p++) { T.p2i[p] = 0; T.p2j[p] = 0; }
  return T;
}

constexpr Tables hT = makeTables();
__constant__ Tables dT = makeTables();

// ======================= device scratch =========================================
#define NMAX   4096
#define NGRID  148
#define NPAIR  231
#define NK     77
#define TLD    79
#define NRED   8

__device__ float g_w[NMAX];
__device__ float g_psum[64];
__device__ float g_invsum;
__device__ unsigned int g_cnt = 0;
__device__ float g_part[NGRID][256 * 80];
__device__ float g_S8[NRED][NPAIR * 80];
__device__ float g_S[NPAIR * NK];
__device__ float g_A[NK * NK];

// ======================= helpers ================================================
__device__ __forceinline__ uint32_t cvta_smem(const void* p) {
  uint32_t a;
  asm("{ .reg .u64 t; cvta.to.shared.u64 t, %1; cvt.u32.u64 %0, t; }"
      : "=r"(a) : "l"(p));
  return a;
}

__device__ __forceinline__ uint32_t bf16x2pack(float lo, float hi) {
  uint32_t r;
  asm("cvt.rn.bf16x2.f32 %0, %1, %2;" : "=r"(r) : "f"(hi), "f"(lo));
  return r;
}

#define LDSM_X4(r0, r1, r2, r3, addr) \
  asm volatile("ldmatrix.sync.aligned.m8n8.x4.shared.b16 {%0,%1,%2,%3}, [%4];" \
               : "=r"(r0), "=r"(r1), "=r"(r2), "=r"(r3) : "r"(addr))

#define MMA_BF16(c, a, b0_, b1_) \
  asm volatile("mma.sync.aligned.m16n8k16.row.col.f32.bf16.bf16.f32 " \
               "{%0,%1,%2,%3}, {%4,%5,%6,%7}, {%8,%9}, {%0,%1,%2,%3};" \
               : "+f"((c)[0]), "+f"((c)[1]), "+f"((c)[2]), "+f"((c)[3]) \
               : "r"((a)[0]), "r"((a)[1]), "r"((a)[2]), "r"((a)[3]), \
                 "r"(b0_), "r"(b1_))

// smem layout bytes (k_main) — unchanged from R12
#define AROW      80
#define A_BYTES   (256 * AROW)
#define B_BYTES   (80 * AROW)
#define OFF_B     (2 * A_BYTES)
#define OFF_PF    (OFF_B + 4 * B_BYTES)
#define OFF_DS    (OFF_PF + 2 * 240 * 4)
#define OFF_WS    (OFF_DS + 3 * 256 * 4)
#define SMEM_MAIN (OFF_WS + 2 * 448 * 4)

// ======================= kernel 1: volumes + fused normalization sum ============
__global__ void __launch_bounds__(256, 1)
k_vols(const float* __restrict__ metric, int n) {
  __shared__ float red[256];
  __shared__ bool amLast;
  const int tid = threadIdx.x;
  const int idx = blockIdx.x * 256 + tid;
  float vol = 0.f;
  if (idx < n) {
    float a[7][7];
#pragma unroll
    for (int r = 0; r < 7; r++)
#pragma unroll
      for (int cc = 0; cc < 7; cc++) a[r][cc] = metric[idx * 49 + r * 7 + cc];
    float det = 1.f;
#pragma unroll
    for (int k = 0; k < 7; k++) {
      float mx = fabsf(a[k][k]);
      int piv = k;
#pragma unroll
      for (int r = k + 1; r < 7; r++) {
        float v = fabsf(a[r][k]);
        if (v > mx) { mx = v; piv = r; }
      }
#pragma unroll
      for (int r = k + 1; r < 7; r++) {
        if (piv == r) {
          det = -det;
#pragma unroll
          for (int cc = k; cc < 7; cc++) {
            float t = a[k][cc]; a[k][cc] = a[r][cc]; a[r][cc] = t;
          }
        }
      }
      float akk = a[k][k];
      det *= akk;
      float inv = (akk != 0.f) ? 1.f / akk : 0.f;
#pragma unroll
      for (int r = k + 1; r < 7; r++) {
        float f = a[r][k] * inv;
#pragma unroll
        for (int cc = k + 1; cc < 7; cc++) a[r][cc] = fmaf(-f, a[k][cc], a[r][cc]);
      }
    }
    vol = sqrtf(fabsf(det));
    g_w[idx] = vol;
  }
  red[tid] = vol;
  __syncthreads();
#pragma unroll
  for (int s = 128; s > 0; s >>= 1) {
    if (tid < s) red[tid] += red[tid + s];
    __syncthreads();
  }
  if (tid == 0) {
    g_psum[blockIdx.x] = red[0];
    __threadfence();
    unsigned int done = atomicAdd(&g_cnt, 1u);
    amLast = (done == gridDim.x - 1);
  }
  __syncthreads();
  if (amLast && tid == 0) {
    g_cnt = 0;
    float s = 0.f;
    for (unsigned int i = 0; i < gridDim.x; i++) s += g_psum[i];
    g_invsum = 1.f / s;
  }
}

// ======================= D-compute: fully unrolled ==============================
template <int C, int T>
__device__ __forceinline__ float dterms(const float (&wi)[21], const float (&wj)[21],
                                        float acc) {
  constexpr int a = hT.ta[C][T];
  constexpr int b = hT.tb[C][T];
  if constexpr (hT.ts[C][T] > 0.f)
    acc = fmaf(wi[a], wj[b], acc);
  else
    acc = fmaf(-wi[a], wj[b], acc);
  if constexpr (T + 1 < 6) return dterms<C, T + 1>(wi, wj, acc);
  return acc;
}

template <int U, int UEND>
__device__ __forceinline__ void dBf16(char* smc, uint32_t rowOff,
                                      const float (&wi)[21], const float (&wj)[21]) {
  float d0 = dterms<2 * U, 0>(wi, wj, 0.0f);
  float d1 = dterms<2 * U + 1, 0>(wi, wj, 0.0f);
  uint32_t hw = bf16x2pack(d0, d1);
  float r0 = d0 - __uint_as_float(hw << 16);
  float r1 = d1 - __uint_as_float(hw & 0xffff0000u);
  uint32_t lw = bf16x2pack(r0, r1);
  *(uint32_t*)(smc + rowOff + 4 * U) = hw;
  *(uint32_t*)(smc + A_BYTES + rowOff + 4 * U) = lw;
  if constexpr (U + 1 < UEND) dBf16<U + 1, UEND>(smc, rowOff, wi, wj);
}

template <int C, int CEND>
__device__ __forceinline__ void dF32(float* ds, int pair,
                                     const float (&wi)[21], const float (&wj)[21]) {
  ds[(C - 32) * 256 + pair] = dterms<C, 0>(wi, wj, 0.0f);
  if constexpr (C + 1 < CEND) dF32<C + 1, CEND>(ds, pair, wi, wj);
}

// ======================= kernel 2: hybrid HMMA + fp32-tail GEMM (R12 verbatim) ==
__global__ void __launch_bounds__(512, 1)
k_main(const float* __restrict__ omega, const float* __restrict__ Phi, int n,
       int chunk) {
  extern __shared__ char smc[];
  const int tid  = threadIdx.x;
  const int w    = tid >> 5;
  const int lane = tid & 31;
  const uint32_t smb = cvta_smem(smc);

  for (int i = tid; i < SMEM_MAIN / 4; i += 512) ((uint32_t*)smc)[i] = 0u;

  int n0 = blockIdx.x * chunk;
  int n1 = n0 + chunk;
  if (n1 > n) n1 = n;

  if (n0 >= n1) {
    __syncthreads();
    for (int i = tid; i < 256 * 80; i += 512) g_part[blockIdx.x][i] = 0.f;
    return;
  }

  const int myPair = w * 16 + (lane & 15);
  const int pi = dT.p2i[myPair];
  const int pj = dT.p2j[myPair];
  const int halfHi = lane >> 4;
  const int g = lane >> 2;
  const int t = lane & 3;

  uint32_t bOff[6];
  bool bAct[6], bIsB[6];
#pragma unroll
  for (int j = 0; j < 6; j++) {
    int idx = tid + j * 512;
    bAct[j] = idx < 2695;
    int k = idx / 35;
    int c = idx - k * 35;
    bIsB[j] = c < 32;
    bOff[j] = bIsB[j] ? (uint32_t)(k * AROW + c * 2)
                      : (uint32_t)((c - 32) * 80 + k);
  }

  const uint32_t aRow  = (uint32_t)(w * 16 + ((lane >> 3) & 1) * 8 + (lane & 7));
  const uint32_t aAddr = smb + aRow * AROW + (uint32_t)(lane >> 4) * 16;
  const uint32_t bRow  = (uint32_t)(((lane >> 4) & 1) * 8 + (lane & 7));
  const uint32_t bAddr0 = smb + OFF_B + bRow * AROW +
                          (uint32_t)((lane >> 3) & 1) * 16;

  float acc[10][4];
#pragma unroll
  for (int a = 0; a < 10; a++)
#pragma unroll
    for (int b = 0; b < 4; b++) acc[a][b] = 0.f;

  float rO = 0.f, rP[6], rWn = 0.f;
#pragma unroll
  for (int j = 0; j < 6; j++) rP[j] = 0.f;
  {
    const float* og = omega + (size_t)n0 * 441;
    if (tid < 441) rO = og[tid];
    const float* pg = Phi + (size_t)n0 * 2695;
#pragma unroll
    for (int j = 0; j < 6; j++)
      if (bAct[j]) rP[j] = pg[tid + j * 512];
    rWn = g_w[n0];
  }
  __syncthreads();

  int buf = 0;
#pragma unroll 1
  for (int nn = n0; nn < n1; nn++) {
    char*  bb = smc + OFF_B + (buf ? 2 * B_BYTES : 0);
    float* pf = (float*)(smc + OFF_PF) + (buf ? 240 : 0);
    float* Ws = (float*)(smc + OFF_WS) + (buf ? 448 : 0);
    float* ds = (float*)(smc + OFF_DS);

    if (tid < 441) Ws[tid] = rO;
    {
      const float wn = rWn;
#pragma unroll
      for (int j = 0; j < 6; j++) {
        if (bAct[j]) {
          float v = rP[j] * wn;
          if (bIsB[j]) {
            __nv_bfloat16 bh = __float2bfloat16(v);
            float res = v - __bfloat162float(bh);
            __nv_bfloat16 bl = __float2bfloat16(res);
            *(__nv_bfloat16*)(bb + bOff[j]) = bh;
            *(__nv_bfloat16*)(bb + B_BYTES + bOff[j]) = bl;
          } else {
            pf[bOff[j]] = v;
          }
        }
      }
    }

    {
      int nx = (nn + 1 < n1) ? nn + 1 : nn;
      const float* og = omega + (size_t)nx * 441;
      if (tid < 441) rO = og[tid];
      const float* pg = Phi + (size_t)nx * 2695;
#pragma unroll
      for (int j = 0; j < 6; j++)
        if (bAct[j]) rP[j] = pg[tid + j * 512];
      rWn = g_w[nx];
    }
    __syncthreads();

    __syncwarp();
    {
      float wi[21], wj[21];
      const float* Wi = &Ws[pi * 21];
      const float* Wj = &Ws[pj * 21];
#pragma unroll
      for (int a = 0; a < 21; a++) { wi[a] = Wi[a]; wj[a] = Wj[a]; }
      const uint32_t rowOff = (uint32_t)(myPair * AROW);
      if (!halfHi) {
        dBf16<0, 9>(smc, rowOff, wi, wj);
      } else {
        dBf16<9, 16>(smc, rowOff, wi, wj);
        dF32<32, 35>(ds, myPair, wi, wj);
      }
    }
    __syncwarp();

    const uint32_t bAddr = bAddr0 + (buf ? (uint32_t)(2 * B_BYTES) : 0u);
#pragma unroll
    for (int ks = 0; ks < 2; ks++) {
      uint32_t ah[4], al[4];
      LDSM_X4(ah[0], ah[1], ah[2], ah[3], aAddr + ks * 32);
      LDSM_X4(al[0], al[1], al[2], al[3], aAddr + A_BYTES + ks * 32);
#pragma unroll
      for (int tp = 0; tp < 5; tp++) {
        uint32_t bh[4], bl[4];
        uint32_t ba = bAddr + (uint32_t)(tp * 16 * AROW) + ks * 32;
        LDSM_X4(bh[0], bh[1], bh[2], bh[3], ba);
        LDSM_X4(bl[0], bl[1], bl[2], bl[3], ba + B_BYTES);
        MMA_BF16(acc[2 * tp],     ah, bh[0], bh[1]);
        MMA_BF16(acc[2 * tp],     ah, bl[0], bl[1]);
        MMA_BF16(acc[2 * tp],     al, bh[0], bh[1]);
        MMA_BF16(acc[2 * tp + 1], ah, bh[2], bh[3]);
        MMA_BF16(acc[2 * tp + 1], ah, bl[2], bl[3]);
        MMA_BF16(acc[2 * tp + 1], al, bh[2], bh[3]);
      }
    }

    {
      const int base = w * 16 + g;
#pragma unroll
      for (int c2 = 0; c2 < 3; c2++) {
        float dr0 = ds[c2 * 256 + base];
        float dr1 = ds[c2 * 256 + base + 8];
        const float* prow = &pf[c2 * 80 + 2 * t];
#pragma unroll
        for (int nt = 0; nt < 10; nt++) {
          float2 pv = *(const float2*)&prow[nt * 8];
          acc[nt][0] = fmaf(dr0, pv.x, acc[nt][0]);
          acc[nt][1] = fmaf(dr0, pv.y, acc[nt][1]);
          acc[nt][2] = fmaf(dr1, pv.x, acc[nt][2]);
          acc[nt][3] = fmaf(dr1, pv.y, acc[nt][3]);
        }
      }
    }
    buf ^= 1;
  }

  {
    const int r0 = w * 16 + g, r1 = r0 + 8;
    float* dst = g_part[blockIdx.x];
#pragma unroll
    for (int nt = 0; nt < 10; nt++) {
      int col = nt * 8 + 2 * t;
      *(float2*)&dst[r0 * 80 + col] = make_float2(acc[nt][0], acc[nt][1]);
      *(float2*)&dst[r1 * 80 + col] = make_float2(acc[nt][2], acc[nt][3]);
    }
  }
}

// ======================= kernel 3a: reduce partials (8-way n-chunk) =============
__global__ void __launch_bounds__(128, 8)
k_reduceS() {
  const int t = blockIdx.x * 128 + threadIdx.x;
  if (t >= NPAIR * 20) return;
  const int p = t / 20;
  const int q = t - p * 20;
  const int y = blockIdx.y;
  const int b0  = (y < 4) ? y * 19 : 76 + (y - 4) * 18;
  const int cnt = (y < 4) ? 19 : 18;
  float4 s = make_float4(0.f, 0.f, 0.f, 0.f);
#pragma unroll 4
  for (int b = 0; b < cnt; b++) {
    float4 v = *(const float4*)&g_part[b0 + b][p * 80 + q * 4];
    s.x += v.x; s.y += v.y; s.z += v.z; s.w += v.w;
  }
  *(float4*)&g_S8[y][p * 80 + q * 4] = s;
}

// ======================= kernel 3b: emit Y + final S ============================
__global__ void k_emitY(float* __restrict__ out, int writeY) {
  int idx = blockIdx.x * blockDim.x + threadIdx.x;
  if (idx >= 441 * 77) return;
  const float inv = g_invsum;
  int i = idx / 1617;
  int rem = idx - i * 1617;
  int j = rem / 77;
  int k = rem - j * 77;
  int lo = i < j ? i : j;
  int hi = i < j ? j : i;
  int p = lo * 21 - lo * (lo - 1) / 2 + (hi - lo);
  int o = p * 80 + k;
  float s = ((g_S8[0][o] + g_S8[1][o]) + (g_S8[2][o] + g_S8[3][o])) +
            ((g_S8[4][o] + g_S8[5][o]) + (g_S8[6][o] + g_S8[7][o]));
  s *= inv;
  if (writeY) out[idx] = (j >= i) ? s : -s;
  if (i <= j) g_S[p * 77 + k] = s;
}

// ======================= kernel 4: build M = S^T diag(m) S ======================
__global__ void __launch_bounds__(128, 1)
k_buildM(float* __restrict__ out, int oM) {
  __shared__ float cs[NPAIR];
  const int k = blockIdx.x;
  const int tid = threadIdx.x;
  for (int p = tid; p < NPAIR; p += 128) {
    float wgt = (dT.p2i[p] == dT.p2j[p]) ? 1.f : 2.f;
    cs[p] = wgt * g_S[p * 77 + k];
  }
  __syncthreads();
  if (tid < 77) {
    float a0 = 0.f, a1 = 0.f, a2 = 0.f, a3 = 0.f;
    int p = 0;
#pragma unroll 4
    for (; p + 4 <= NPAIR; p += 4) {
      a0 = fmaf(cs[p],     g_S[p * 77 + tid],       a0);
      a1 = fmaf(cs[p + 1], g_S[(p + 1) * 77 + tid], a1);
      a2 = fmaf(cs[p + 2], g_S[(p + 2) * 77 + tid], a2);
      a3 = fmaf(cs[p + 3], g_S[(p + 3) * 77 + tid], a3);
    }
    for (; p < NPAIR; p++) a0 = fmaf(cs[p], g_S[p * 77 + tid], a0);
    float v = (a0 + a1) + (a2 + a3);
    out[oM + k * 77 + tid] = v;
    g_A[k * 77 + tid] = v;
  }
}

// ======================= kernel 5: tridiag (4 barriers/step) + Sturm bisect =====
#define NPROBE 13
#define NROUND 10

__global__ void __launch_bounds__(1024, 1)
k_eig(float* __restrict__ out, int oE) {
  __shared__ float A[NK * TLD];
  __shared__ float us[80], pp[80], ps[80];
  __shared__ float dd[NK], ee[NK], e2s[NK];
  __shared__ float lo_s[NK], hi_s[NK];
  __shared__ float xs[NK * NPROBE];
  __shared__ int   cs[NK * NPROBE];
  __shared__ float sh_scTb, gl_s, gh_s, piv_s;
  __shared__ int   skip;
  const int tid  = threadIdx.x;
  const int lane = tid & 31;
  const int warp = tid >> 5;
  const int rrow = tid >> 3;   // matvec: 8 threads per row
  const int rq   = tid & 7;

  for (int idx = tid; idx < NK * NK; idx += 1024) {
    int r = idx / NK, c = idx - r * NK;
    A[r * TLD + c] = g_A[idx];
  }
  __syncthreads();

  // ---- Householder tridiagonalization: 4 barriers per step ----
  float scTb0 = 0.f;  // warp0-private copy of scTb (valid within a step)
#pragma unroll 1
  for (int k = 0; k < 75; k++) {
    const int m = 76 - k;

    // phase 1 (warp 0 only): sigma, alpha, scTb, u
    if (warp == 0) {
      float v0s = 0.f, v1s = 0.f, v2s = 0.f;
      if (lane < m)      v0s = A[(k + 1 + lane) * TLD + k];
      if (lane + 32 < m) v1s = A[(k + 33 + lane) * TLD + k];
      if (lane + 64 < m) v2s = A[(k + 65 + lane) * TLD + k];
      float sig = v0s * v0s + v1s * v1s + v2s * v2s;
#pragma unroll
      for (int o = 16; o; o >>= 1) sig += __shfl_xor_sync(0xffffffffu, sig, o);
      float v0 = __shfl_sync(0xffffffffu, v0s, 0);
      if (lane == 0) dd[k] = A[k * TLD + k];
      if (sig < 1e-30f) {
        if (lane == 0) { ee[k] = 0.f; skip = 1; }
      } else {
        float alpha = -copysignf(sqrtf(sig), v0);
        float beta  = 2.f * (sig - v0 * alpha);
        scTb0 = 2.f / beta;
        if (lane == 0) { ee[k] = alpha; sh_scTb = scTb0; skip = 0; }
        if (lane < m)      us[lane]      = (lane == 0) ? v0s - alpha : v0s;
        if (lane + 32 < m) us[lane + 32] = v1s;
        if (lane + 64 < m) us[lane + 64] = v2s;
      }
    }
    __syncthreads();   // B1: us, sh_scTb, skip visible
    if (skip) continue;

    // phase 2 (all): matvec pp = scTb * A(sub) * u, 8 threads per row
    {
      float a0 = 0.f, a1 = 0.f;
      if (rrow < m) {
        const float* row = &A[(k + 1 + rrow) * TLD + (k + 1)];
        int j = rq;
        for (; j + 8 < m; j += 16) {   // guard covers max offset +8 (R14 fix)
          a0 = fmaf(row[j],     us[j],     a0);
          a1 = fmaf(row[j + 8], us[j + 8], a1);
        }
        for (; j < m; j += 8) a0 = fmaf(row[j], us[j], a0);
      }
      float s = a0 + a1;
      s += __shfl_xor_sync(0xffffffffu, s, 1);
      s += __shfl_xor_sync(0xffffffffu, s, 2);
      s += __shfl_xor_sync(0xffffffffu, s, 4);
      if (rrow < m && rq == 0) pp[rrow] = s * sh_scTb;
    }
    __syncthreads();   // B2: pp visible

    // phase 3 (warp 0 only): upT reduce + ps = pp - kappa*us
    if (warp == 0) {
      float p0 = 0.f, p1 = 0.f, p2 = 0.f;
      float u0 = 0.f, u1 = 0.f, u2 = 0.f;
      if (lane < m)      { p0 = pp[lane];      u0 = us[lane]; }
      if (lane + 32 < m) { p1 = pp[lane + 32]; u1 = us[lane + 32]; }
      if (lane + 64 < m) { p2 = pp[lane + 64]; u2 = us[lane + 64]; }
      float t = p0 * u0 + p1 * u1 + p2 * u2;
#pragma unroll
      for (int o = 16; o; o >>= 1) t += __shfl_xor_sync(0xffffffffu, t, o);
      float kappa = t * scTb0 * 0.5f;
      if (lane < m)      ps[lane]      = p0 - kappa * u0;
      if (lane + 32 < m) ps[lane + 32] = p1 - kappa * u1;
      if (lane + 64 < m) ps[lane + 64] = p2 - kappa * u2;
    }
    __syncthreads();   // B3: ps visible

    // phase 4 (all): rank-2 update, warp per row
    for (int i = warp; i < m; i += 32) {
      const float ui = us[i], pi_ = ps[i];
      float* rowA = &A[(k + 1 + i) * TLD + (k + 1)];
      for (int j = lane; j < m; j += 32)
        rowA[j] -= ui * ps[j] + pi_ * us[j];
    }
    __syncthreads();   // B4: A updated
  }

  if (tid == 0) {
    dd[75] = A[75 * TLD + 75];
    ee[75] = A[76 * TLD + 75];
    dd[76] = A[76 * TLD + 76];
    ee[76] = 0.f;
  }
  __syncthreads();
  if (tid < NK) e2s[tid] = ee[tid] * ee[tid];
  __syncthreads();

  // ---- Sturm multisection eigenvalues ----
  if (tid == 0) {
    float gl = 3.4e38f, gh = -3.4e38f, me2 = 0.f;
    for (int i = 0; i < NK; i++) {
      float eprev = (i > 0) ? sqrtf(e2s[i - 1]) : 0.f;
      float ecur  = (i < 76) ? sqrtf(e2s[i]) : 0.f;
      float r = eprev + ecur;
      gl = fminf(gl, dd[i] - r);
      gh = fmaxf(gh, dd[i] + r);
      me2 = fmaxf(me2, e2s[i]);
    }
    float wid = fmaxf(gh - gl, 1e-20f);
    gl_s = gl - 1e-3f * wid;
    gh_s = gh + 1e-3f * wid;
    piv_s = fmaxf(me2 * 1.2e-38f, 1e-37f);
  }
  __syncthreads();
  if (tid < NK) { lo_s[tid] = gl_s; hi_s[tid] = gh_s; }
  __syncthreads();

  const int gg = tid / NPROBE;
  const int jj = tid - gg * NPROBE;
  const bool act = (gg < NK);
  const float pivmin = piv_s;
  const float cj = (float)(jj + 1) / (float)(NPROBE + 1);

#pragma unroll 1
  for (int r = 0; r < NROUND; r++) {
    if (act) {
      float lo = lo_s[gg], hi = hi_s[gg];
      float x = lo + (hi - lo) * cj;
      xs[tid] = x;
      float q = dd[0] - x;
      int cnt = (q < 0.f);
#pragma unroll 4
      for (int i = 1; i < NK; i++) {
        float aq = fabsf(q);
        if (aq < pivmin) q = -pivmin;
        q = dd[i] - x - __fdividef(e2s[i - 1], q);
        cnt += (q < 0.f);
      }
      cs[tid] = cnt;
    }
    __syncthreads();
    if (act && jj == 0) {
      float lo = lo_s[gg], hi = hi_s[gg];
      for (int u = 0; u < NPROBE; u++) {
        int c = cs[gg * NPROBE + u];
        float x = xs[gg * NPROBE + u];
        if (c <= gg) lo = x;
        else { hi = x; break; }
      }
      lo_s[gg] = lo;
      hi_s[gg] = hi;
    }
    __syncthreads();
  }

  if (act && jj == 0) out[oE + (76 - gg)] = 0.5f * (lo_s[gg] + hi_s[gg]);
}

// ======================= launch =================================================
extern "C" void kernel_launch(void* const* d_in, const int* in_sizes, int n_in,
                              void* d_out, int out_size) {
  const float* omega  = (const float*)d_in[0];
  const float* Phi    = (const float*)d_in[1];
  const float* metric = (const float*)d_in[2];
  int n = in_sizes[2] / 49;
  if (n > NMAX) n = NMAX;

  float* out = (float*)d_out;
  int oE = out_size - 77;
  int oM = oE - 77 * 77;
  int writeY = (out_size >= 33957 + 77 * 77 + 77) ? 1 : 0;

  int nb = (n + 255) / 256;
  k_vols<<<nb, 256>>>(metric, n);

  int chunk = (n + NGRID - 1) / NGRID;
  cudaFuncSetAttribute(k_main, cudaFuncAttributeMaxDynamicSharedMemorySize,
                       SMEM_MAIN);
  k_main<<<NGRID, 512, SMEM_MAIN>>>(omega, Phi, n, chunk);

  k_reduceS<<<dim3((NPAIR * 20 + 127) / 128, NRED), 128>>>();
  k_emitY<<<(441 * 77 + 255) / 256, 256>>>(out, writeY);

  k_buildM<<<77, 128>>>(out, oM);
  k_eig<<<1, 1024>>>(out, oE);
}

// round 16
// speedup vs baseline: 1.2278x; 1.0338x over previous
#include <cuda_runtime.h>
#include <cuda_bf16.h>
#include <math.h>
#include <stdint.h>

// ======================= compile-time structure constants =======================
struct Tables {
  signed char   ta[35][6];
  signed char   tb[35][6];
  float         ts[35][6];
  unsigned char p2i[256];
  unsigned char p2j[256];
};

constexpr Tables makeTables() {
  Tables T{};
  int c = 0;
  for (int x = 0; x < 7; x++)
    for (int y = x + 1; y < 7; y++)
      for (int z = y + 1; z < 7; z++) {
        int comp[4] = {0, 0, 0, 0};
        int m = 0;
        for (int e = 0; e < 7; e++)
          if (e != x && e != y && e != z) comp[m++] = e;
        int t = 0;
        for (int u = 0; u < 4; u++)
          for (int v = u + 1; v < 4; v++) {
            int a0 = comp[u], a1 = comp[v];
            int b0 = -1, b1 = -1;
            for (int e = 0; e < 4; e++) {
              if (e != u && e != v) { if (b0 < 0) b0 = comp[e]; else b1 = comp[e]; }
            }
            int perm[7] = {a0, a1, b0, b1, x, y, z};
            int inv = 0;
            for (int q = 0; q < 7; q++)
              for (int r = q + 1; r < 7; r++)
                if (perm[q] > perm[r]) inv++;
            T.ts[c][t] = (inv & 1) ? -1.0f : 1.0f;
            T.ta[c][t] = (signed char)(6 * a0 - a0 * (a0 - 1) / 2 + (a1 - a0 - 1));
            T.tb[c][t] = (signed char)(6 * b0 - b0 * (b0 - 1) / 2 + (b1 - b0 - 1));
            t++;
          }
        c++;
      }
  int p = 0;
  for (int i = 0; i < 21; i++)
    for (int j = i; j < 21; j++) {
      T.p2i[p] = (unsigned char)i;
      T.p2j[p] = (unsigned char)j;
      p++;
    }
  for (; p < 256; p++) { T.p2i[p] = 0; T.p2j[p] = 0; }
  return T;
}

constexpr Tables hT = makeTables();
__constant__ Tables dT = makeTables();

// ======================= device scratch =========================================
#define NMAX   4096
#define NGRID  148
#define NPAIR  231
#define NK     77
#define TLD    79
#define NRED   8

__device__ float g_psum[NGRID];
__device__ float g_invsum;
__device__ float g_part[NGRID][256 * 80];
__device__ float g_S8[NRED][NPAIR * 80];
__device__ float g_S[NPAIR * NK];
__device__ float g_A[NK * NK];

// ======================= helpers ================================================
__device__ __forceinline__ uint32_t cvta_smem(const void* p) {
  uint32_t a;
  asm("{ .reg .u64 t; cvta.to.shared.u64 t, %1; cvt.u32.u64 %0, t; }"
      : "=r"(a) : "l"(p));
  return a;
}

__device__ __forceinline__ uint32_t bf16x2pack(float lo, float hi) {
  uint32_t r;
  asm("cvt.rn.bf16x2.f32 %0, %1, %2;" : "=r"(r) : "f"(hi), "f"(lo));
  return r;
}

#define LDSM_X4(r0, r1, r2, r3, addr) \
  asm volatile("ldmatrix.sync.aligned.m8n8.x4.shared.b16 {%0,%1,%2,%3}, [%4];" \
               : "=r"(r0), "=r"(r1), "=r"(r2), "=r"(r3) : "r"(addr))

#define MMA_BF16(c, a, b0_, b1_) \
  asm volatile("mma.sync.aligned.m16n8k16.row.col.f32.bf16.bf16.f32 " \
               "{%0,%1,%2,%3}, {%4,%5,%6,%7}, {%8,%9}, {%0,%1,%2,%3};" \
               : "+f"((c)[0]), "+f"((c)[1]), "+f"((c)[2]), "+f"((c)[3]) \
               : "r"((a)[0]), "r"((a)[1]), "r"((a)[2]), "r"((a)[3]), \
                 "r"(b0_), "r"(b1_))

// smem layout bytes (k_main)
#define AROW      80
#define A_BYTES   (256 * AROW)
#define B_BYTES   (80 * AROW)
#define OFF_B     (2 * A_BYTES)
#define OFF_PF    (OFF_B + 4 * B_BYTES)
#define OFF_DS    (OFF_PF + 2 * 240 * 4)
#define OFF_WS    (OFF_DS + 3 * 256 * 4)
#define SMEM_MAIN (OFF_WS + 2 * 448 * 4)

// ======================= D-compute: fully unrolled ==============================
template <int C, int T>
__device__ __forceinline__ float dterms(const float (&wi)[21], const float (&wj)[21],
                                        float acc) {
  constexpr int a = hT.ta[C][T];
  constexpr int b = hT.tb[C][T];
  if constexpr (hT.ts[C][T] > 0.f)
    acc = fmaf(wi[a], wj[b], acc);
  else
    acc = fmaf(-wi[a], wj[b], acc);
  if constexpr (T + 1 < 6) return dterms<C, T + 1>(wi, wj, acc);
  return acc;
}

template <int U, int UEND>
__device__ __forceinline__ void dBf16(char* smc, uint32_t rowOff,
                                      const float (&wi)[21], const float (&wj)[21]) {
  float d0 = dterms<2 * U, 0>(wi, wj, 0.0f);
  float d1 = dterms<2 * U + 1, 0>(wi, wj, 0.0f);
  uint32_t hw = bf16x2pack(d0, d1);
  float r0 = d0 - __uint_as_float(hw << 16);
  float r1 = d1 - __uint_as_float(hw & 0xffff0000u);
  uint32_t lw = bf16x2pack(r0, r1);
  *(uint32_t*)(smc + rowOff + 4 * U) = hw;
  *(uint32_t*)(smc + A_BYTES + rowOff + 4 * U) = lw;
  if constexpr (U + 1 < UEND) dBf16<U + 1, UEND>(smc, rowOff, wi, wj);
}

template <int C, int CEND>
__device__ __forceinline__ void dF32(float* ds, int pair,
                                     const float (&wi)[21], const float (&wj)[21]) {
  ds[(C - 32) * 256 + pair] = dterms<C, 0>(wi, wj, 0.0f);
  if constexpr (C + 1 < CEND) dF32<C + 1, CEND>(ds, pair, wi, wj);
}

// ======================= kernel 1: hybrid HMMA GEMM + inlined vols ==============
// grid 148 x 512. Prologue: block computes its own chunk's MC volumes (<=32,
// register LU), warp0 shuffle-sums to g_psum. Normalization deferred to emitY.
__global__ void __launch_bounds__(512, 1)
k_main(const float* __restrict__ omega, const float* __restrict__ Phi,
       const float* __restrict__ metric, int n, int chunk) {
  extern __shared__ char smc[];
  __shared__ float wv[32];
  const int tid  = threadIdx.x;
  const int w    = tid >> 5;
  const int lane = tid & 31;
  const uint32_t smb = cvta_smem(smc);

  for (int i = tid; i < SMEM_MAIN / 4; i += 512) ((uint32_t*)smc)[i] = 0u;

  int n0 = blockIdx.x * chunk;
  int n1 = n0 + chunk;
  if (n1 > n) n1 = n;

  if (n0 >= n1) {
    if (tid == 0) g_psum[blockIdx.x] = 0.f;
    __syncthreads();
    for (int i = tid; i < 256 * 80; i += 512) g_part[blockIdx.x][i] = 0.f;
    return;
  }

  const int cnt = n1 - n0;  // <= 32 by construction (chunk = ceil(n/148))
  // ---- per-block Monte-Carlo volumes (static-index pivoted LU, registers) ----
  float myVol = 0.f;
  if (tid < cnt) {
    const float* mp = metric + (size_t)(n0 + tid) * 49;
    float a[7][7];
#pragma unroll
    for (int r = 0; r < 7; r++)
#pragma unroll
      for (int cc = 0; cc < 7; cc++) a[r][cc] = mp[r * 7 + cc];
    float det = 1.f;
#pragma unroll
    for (int k = 0; k < 7; k++) {
      float mx = fabsf(a[k][k]);
      int piv = k;
#pragma unroll
      for (int r = k + 1; r < 7; r++) {
        float v = fabsf(a[r][k]);
        if (v > mx) { mx = v; piv = r; }
      }
#pragma unroll
      for (int r = k + 1; r < 7; r++) {
        if (piv == r) {
          det = -det;
#pragma unroll
          for (int cc = k; cc < 7; cc++) {
            float t = a[k][cc]; a[k][cc] = a[r][cc]; a[r][cc] = t;
          }
        }
      }
      float akk = a[k][k];
      det *= akk;
      float inv = (akk != 0.f) ? 1.f / akk : 0.f;
#pragma unroll
      for (int r = k + 1; r < 7; r++) {
        float f = a[r][k] * inv;
#pragma unroll
        for (int cc = k + 1; cc < 7; cc++) a[r][cc] = fmaf(-f, a[k][cc], a[r][cc]);
      }
    }
    myVol = sqrtf(fabsf(det));
    wv[tid] = myVol;
  }
  if (w == 0) {
    float s = myVol;
#pragma unroll
    for (int o = 16; o; o >>= 1) s += __shfl_xor_sync(0xffffffffu, s, o);
    if (lane == 0) g_psum[blockIdx.x] = s;
  }

  const int myPair = w * 16 + (lane & 15);
  const int pi = dT.p2i[myPair];
  const int pj = dT.p2j[myPair];
  const int halfHi = lane >> 4;
  const int g = lane >> 2;
  const int t = lane & 3;

  uint32_t bOff[6];
  bool bAct[6], bIsB[6];
#pragma unroll
  for (int j = 0; j < 6; j++) {
    int idx = tid + j * 512;
    bAct[j] = idx < 2695;
    int k = idx / 35;
    int c = idx - k * 35;
    bIsB[j] = c < 32;
    bOff[j] = bIsB[j] ? (uint32_t)(k * AROW + c * 2)
                      : (uint32_t)((c - 32) * 80 + k);
  }

  const uint32_t aRow  = (uint32_t)(w * 16 + ((lane >> 3) & 1) * 8 + (lane & 7));
  const uint32_t aAddr = smb + aRow * AROW + (uint32_t)(lane >> 4) * 16;
  const uint32_t bRow  = (uint32_t)(((lane >> 4) & 1) * 8 + (lane & 7));
  const uint32_t bAddr0 = smb + OFF_B + bRow * AROW +
                          (uint32_t)((lane >> 3) & 1) * 16;

  float acc[10][4];
#pragma unroll
  for (int a = 0; a < 10; a++)
#pragma unroll
    for (int b = 0; b < 4; b++) acc[a][b] = 0.f;

  __syncthreads();   // zero-init + wv visible

  float rO = 0.f, rP[6], rWn = 0.f;
#pragma unroll
  for (int j = 0; j < 6; j++) rP[j] = 0.f;
  {
    const float* og = omega + (size_t)n0 * 441;
    if (tid < 441) rO = og[tid];
    const float* pg = Phi + (size_t)n0 * 2695;
#pragma unroll
    for (int j = 0; j < 6; j++)
      if (bAct[j]) rP[j] = pg[tid + j * 512];
    rWn = wv[0];
  }

  int buf = 0;
#pragma unroll 1
  for (int nn = n0; nn < n1; nn++) {
    char*  bb = smc + OFF_B + (buf ? 2 * B_BYTES : 0);
    float* pf = (float*)(smc + OFF_PF) + (buf ? 240 : 0);
    float* Ws = (float*)(smc + OFF_WS) + (buf ? 448 : 0);
    float* ds = (float*)(smc + OFF_DS);

    if (tid < 441) Ws[tid] = rO;
    {
      const float wn = rWn;
#pragma unroll
      for (int j = 0; j < 6; j++) {
        if (bAct[j]) {
          float v = rP[j] * wn;
          if (bIsB[j]) {
            __nv_bfloat16 bh = __float2bfloat16(v);
            float res = v - __bfloat162float(bh);
            __nv_bfloat16 bl = __float2bfloat16(res);
            *(__nv_bfloat16*)(bb + bOff[j]) = bh;
            *(__nv_bfloat16*)(bb + B_BYTES + bOff[j]) = bl;
          } else {
            pf[bOff[j]] = v;
          }
        }
      }
    }

    {
      int nx = (nn + 1 < n1) ? nn + 1 : nn;
      const float* og = omega + (size_t)nx * 441;
      if (tid < 441) rO = og[tid];
      const float* pg = Phi + (size_t)nx * 2695;
#pragma unroll
      for (int j = 0; j < 6; j++)
        if (bAct[j]) rP[j] = pg[tid + j * 512];
      rWn = wv[nx - n0];
    }
    __syncthreads();

    __syncwarp();
    {
      float wi[21], wj[21];
      const float* Wi = &Ws[pi * 21];
      const float* Wj = &Ws[pj * 21];
#pragma unroll
      for (int a = 0; a < 21; a++) { wi[a] = Wi[a]; wj[a] = Wj[a]; }
      const uint32_t rowOff = (uint32_t)(myPair * AROW);
      if (!halfHi) {
        dBf16<0, 9>(smc, rowOff, wi, wj);
      } else {
        dBf16<9, 16>(smc, rowOff, wi, wj);
        dF32<32, 35>(ds, myPair, wi, wj);
      }
    }
    __syncwarp();

    const uint32_t bAddr = bAddr0 + (buf ? (uint32_t)(2 * B_BYTES) : 0u);
#pragma unroll
    for (int ks = 0; ks < 2; ks++) {
      uint32_t ah[4], al[4];
      LDSM_X4(ah[0], ah[1], ah[2], ah[3], aAddr + ks * 32);
      LDSM_X4(al[0], al[1], al[2], al[3], aAddr + A_BYTES + ks * 32);
#pragma unroll
      for (int tp = 0; tp < 5; tp++) {
        uint32_t bh[4], bl[4];
        uint32_t ba = bAddr + (uint32_t)(tp * 16 * AROW) + ks * 32;
        LDSM_X4(bh[0], bh[1], bh[2], bh[3], ba);
        LDSM_X4(bl[0], bl[1], bl[2], bl[3], ba + B_BYTES);
        MMA_BF16(acc[2 * tp],     ah, bh[0], bh[1]);
        MMA_BF16(acc[2 * tp],     ah, bl[0], bl[1]);
        MMA_BF16(acc[2 * tp],     al, bh[0], bh[1]);
        MMA_BF16(acc[2 * tp + 1], ah, bh[2], bh[3]);
        MMA_BF16(acc[2 * tp + 1], ah, bl[2], bl[3]);
        MMA_BF16(acc[2 * tp + 1], al, bh[2], bh[3]);
      }
    }

    {
      const int base = w * 16 + g;
#pragma unroll
      for (int c2 = 0; c2 < 3; c2++) {
        float dr0 = ds[c2 * 256 + base];
        float dr1 = ds[c2 * 256 + base + 8];
        const float* prow = &pf[c2 * 80 + 2 * t];
#pragma unroll
        for (int nt = 0; nt < 10; nt++) {
          float2 pv = *(const float2*)&prow[nt * 8];
          acc[nt][0] = fmaf(dr0, pv.x, acc[nt][0]);
          acc[nt][1] = fmaf(dr0, pv.y, acc[nt][1]);
          acc[nt][2] = fmaf(dr1, pv.x, acc[nt][2]);
          acc[nt][3] = fmaf(dr1, pv.y, acc[nt][3]);
        }
      }
    }
    buf ^= 1;
  }

  {
    const int r0 = w * 16 + g, r1 = r0 + 8;
    float* dst = g_part[blockIdx.x];
#pragma unroll
    for (int nt = 0; nt < 10; nt++) {
      int col = nt * 8 + 2 * t;
      *(float2*)&dst[r0 * 80 + col] = make_float2(acc[nt][0], acc[nt][1]);
      *(float2*)&dst[r1 * 80 + col] = make_float2(acc[nt][2], acc[nt][3]);
    }
  }
}

// ======================= kernel 2a: reduce partials + invsum ====================
__global__ void __launch_bounds__(128, 8)
k_reduceS() {
  // block (0,0) warp 0 additionally folds the 148 volume partial sums
  if (blockIdx.x == 0 && blockIdx.y == 0 && threadIdx.x < 32) {
    float s = 0.f;
    for (int i = threadIdx.x; i < NGRID; i += 32) s += g_psum[i];
#pragma unroll
    for (int o = 16; o; o >>= 1) s += __shfl_xor_sync(0xffffffffu, s, o);
    if (threadIdx.x == 0) g_invsum = 1.f / s;
  }
  const int t = blockIdx.x * 128 + threadIdx.x;
  if (t >= NPAIR * 20) return;
  const int p = t / 20;
  const int q = t - p * 20;
  const int y = blockIdx.y;
  const int b0  = (y < 4) ? y * 19 : 76 + (y - 4) * 18;
  const int cnt = (y < 4) ? 19 : 18;
  float4 s = make_float4(0.f, 0.f, 0.f, 0.f);
#pragma unroll 4
  for (int b = 0; b < cnt; b++) {
    float4 v = *(const float4*)&g_part[b0 + b][p * 80 + q * 4];
    s.x += v.x; s.y += v.y; s.z += v.z; s.w += v.w;
  }
  *(float4*)&g_S8[y][p * 80 + q * 4] = s;
}

// ======================= kernel 2b: emit Y + final S ============================
__global__ void k_emitY(float* __restrict__ out, int writeY) {
  int idx = blockIdx.x * blockDim.x + threadIdx.x;
  if (idx >= 441 * 77) return;
  const float inv = g_invsum;
  int i = idx / 1617;
  int rem = idx - i * 1617;
  int j = rem / 77;
  int k = rem - j * 77;
  int lo = i < j ? i : j;
  int hi = i < j ? j : i;
  int p = lo * 21 - lo * (lo - 1) / 2 + (hi - lo);
  int o = p * 80 + k;
  float s = ((g_S8[0][o] + g_S8[1][o]) + (g_S8[2][o] + g_S8[3][o])) +
            ((g_S8[4][o] + g_S8[5][o]) + (g_S8[6][o] + g_S8[7][o]));
  s *= inv;
  if (writeY) out[idx] = (j >= i) ? s : -s;
  if (i <= j) g_S[p * 77 + k] = s;
}

// ======================= kernel 3: build M = S^T diag(m) S ======================
__global__ void __launch_bounds__(128, 1)
k_buildM(float* __restrict__ out, int oM) {
  __shared__ float cs[NPAIR];
  const int k = blockIdx.x;
  const int tid = threadIdx.x;
  for (int p = tid; p < NPAIR; p += 128) {
    float wgt = (dT.p2i[p] == dT.p2j[p]) ? 1.f : 2.f;
    cs[p] = wgt * g_S[p * 77 + k];
  }
  __syncthreads();
  if (tid < 77) {
    float a0 = 0.f, a1 = 0.f, a2 = 0.f, a3 = 0.f;
    int p = 0;
#pragma unroll 4
    for (; p + 4 <= NPAIR; p += 4) {
      a0 = fmaf(cs[p],     g_S[p * 77 + tid],       a0);
      a1 = fmaf(cs[p + 1], g_S[(p + 1) * 77 + tid], a1);
      a2 = fmaf(cs[p + 2], g_S[(p + 2) * 77 + tid], a2);
      a3 = fmaf(cs[p + 3], g_S[(p + 3) * 77 + tid], a3);
    }
    for (; p < NPAIR; p++) a0 = fmaf(cs[p], g_S[p * 77 + tid], a0);
    float v = (a0 + a1) + (a2 + a3);
    out[oM + k * 77 + tid] = v;
    g_A[k * 77 + tid] = v;
  }
}

// ======================= kernel 4: tridiag (3 barriers/step) + Sturm bisect =====
#define NPROBE 13
#define NROUND 9

__global__ void __launch_bounds__(1024, 1)
k_eig(float* __restrict__ out, int oE) {
  __shared__ float A[NK * TLD];
  __shared__ float us[80], pp[80];
  __shared__ float dd[NK], ee[NK], e2s[NK];
  __shared__ float lo_s[NK], hi_s[NK];
  __shared__ float xs[NK * NPROBE];
  __shared__ int   cs[NK * NPROBE];
  __shared__ float gl_s, gh_s, piv_s;
  const int tid  = threadIdx.x;
  const int lane = tid & 31;
  const int warp = tid >> 5;
  const int rrow = tid >> 3;   // matvec: 8 threads per row
  const int rq   = tid & 7;

  for (int idx = tid; idx < NK * NK; idx += 1024) {
    int r = idx / NK, c = idx - r * NK;
    A[r * TLD + c] = g_A[idx];
  }
  __syncthreads();

  // ---- Householder tridiagonalization: 3 barriers per step ----
#pragma unroll 1
  for (int k = 0; k < 75; k++) {
    const int m = 76 - k;

    // Phase A (every warp, redundant -> bit-identical): sigma, alpha, scTb
    float v0s = 0.f, v1s = 0.f, v2s = 0.f;
    if (lane < m)      v0s = A[(k + 1 + lane) * TLD + k];
    if (lane + 32 < m) v1s = A[(k + 33 + lane) * TLD + k];
    if (lane + 64 < m) v2s = A[(k + 65 + lane) * TLD + k];
    float sig = v0s * v0s + v1s * v1s + v2s * v2s;
#pragma unroll
    for (int o = 16; o; o >>= 1) sig += __shfl_xor_sync(0xffffffffu, sig, o);
    float v0 = __shfl_sync(0xffffffffu, v0s, 0);
    const bool skip = (sig < 1e-30f);
    float scTb = 0.f;
    if (!skip) {
      float alpha = -copysignf(sqrtf(sig), v0);
      scTb = 2.f / (2.f * (sig - v0 * alpha));
      if (warp == 0) {
        if (lane == 0) { dd[k] = A[k * TLD + k]; ee[k] = alpha; }
        if (lane < m)      us[lane]      = (lane == 0) ? v0s - alpha : v0s;
        if (lane + 32 < m) us[lane + 32] = v1s;
        if (lane + 64 < m) us[lane + 64] = v2s;
      }
    } else {
      if (warp == 0 && lane == 0) { dd[k] = A[k * TLD + k]; ee[k] = 0.f; }
    }
    if (skip) continue;   // uniform (identical sig in every warp)
    __syncthreads();      // B1: us visible

    // Phase B (all): matvec pp = scTb * A(sub) * u, 8 threads per row
    {
      float a0 = 0.f, a1 = 0.f;
      if (rrow < m) {
        const float* row = &A[(k + 1 + rrow) * TLD + (k + 1)];
        int j = rq;
        for (; j + 8 < m; j += 16) {
          a0 = fmaf(row[j],     us[j],     a0);
          a1 = fmaf(row[j + 8], us[j + 8], a1);
        }
        for (; j < m; j += 8) a0 = fmaf(row[j], us[j], a0);
      }
      float s = a0 + a1;
      s += __shfl_xor_sync(0xffffffffu, s, 1);
      s += __shfl_xor_sync(0xffffffffu, s, 2);
      s += __shfl_xor_sync(0xffffffffu, s, 4);
      if (rrow < m && rq == 0) pp[rrow] = s * scTb;
    }
    __syncthreads();      // B2: pp visible

    // Phase C (all): per-warp redundant kappa, then rank-2 update
    {
      float p0 = 0.f, p1 = 0.f, p2 = 0.f;
      float u0 = 0.f, u1 = 0.f, u2 = 0.f;
      if (lane < m)      { p0 = pp[lane];      u0 = us[lane]; }
      if (lane + 32 < m) { p1 = pp[lane + 32]; u1 = us[lane + 32]; }
      if (lane + 64 < m) { p2 = pp[lane + 64]; u2 = us[lane + 64]; }
      float t = p0 * u0 + p1 * u1 + p2 * u2;
#pragma unroll
      for (int o = 16; o; o >>= 1) t += __shfl_xor_sync(0xffffffffu, t, o);
      const float twoKappa = t * scTb;   // 2*kappa = upT*scTb
      // A_ij -= u_i*pp_j + (pp_i - 2k*u_i)*u_j   (== u_i*ps_j + ps_i*u_j)
      for (int i = warp; i < m; i += 32) {
        const float ui = us[i];
        const float qi = pp[i] - twoKappa * ui;
        float* rowA = &A[(k + 1 + i) * TLD + (k + 1)];
        for (int j = lane; j < m; j += 32)
          rowA[j] -= ui * pp[j] + qi * us[j];
      }
    }
    __syncthreads();      // B3: A updated
  }

  if (tid == 0) {
    dd[75] = A[75 * TLD + 75];
    ee[75] = A[76 * TLD + 75];
    dd[76] = A[76 * TLD + 76];
    ee[76] = 0.f;
  }
  __syncthreads();
  if (tid < NK) e2s[tid] = ee[tid] * ee[tid];
  __syncthreads();

  // ---- Sturm multisection eigenvalues ----
  if (tid == 0) {
    float gl = 3.4e38f, gh = -3.4e38f, me2 = 0.f;
    for (int i = 0; i < NK; i++) {
      float eprev = (i > 0) ? sqrtf(e2s[i - 1]) : 0.f;
      float ecur  = (i < 76) ? sqrtf(e2s[i]) : 0.f;
      float r = eprev + ecur;
      gl = fminf(gl, dd[i] - r);
      gh = fmaxf(gh, dd[i] + r);
      me2 = fmaxf(me2, e2s[i]);
    }
    float wid = fmaxf(gh - gl, 1e-20f);
    gl_s = gl - 1e-3f * wid;
    gh_s = gh + 1e-3f * wid;
    piv_s = fmaxf(me2 * 1.2e-38f, 1e-37f);
  }
  __syncthreads();
  if (tid < NK) { lo_s[tid] = gl_s; hi_s[tid] = gh_s; }
  __syncthreads();

  const int gg = tid / NPROBE;
  const int jj = tid - gg * NPROBE;
  const bool act = (gg < NK);
  const float pivmin = piv_s;
  const float cj = (float)(jj + 1) / (float)(NPROBE + 1);

#pragma unroll 1
  for (int r = 0; r < NROUND; r++) {
    if (act) {
      float lo = lo_s[gg], hi = hi_s[gg];
      float x = lo + (hi - lo) * cj;
      xs[tid] = x;
      float q = dd[0] - x;
      int cnt = (q < 0.f);
#pragma unroll 4
      for (int i = 1; i < NK; i++) {
        float aq = fabsf(q);
        if (aq < pivmin) q = -pivmin;
        q = dd[i] - x - __fdividef(e2s[i - 1], q);
        cnt += (q < 0.f);
      }
      cs[tid] = cnt;
    }
    __syncthreads();
    if (act && jj == 0) {
      float lo = lo_s[gg], hi = hi_s[gg];
      for (int u = 0; u < NPROBE; u++) {
        int c = cs[gg * NPROBE + u];
        float x = xs[gg * NPROBE + u];
        if (c <= gg) lo = x;
        else { hi = x; break; }
      }
      lo_s[gg] = lo;
      hi_s[gg] = hi;
    }
    __syncthreads();
  }

  if (act && jj == 0) out[oE + (76 - gg)] = 0.5f * (lo_s[gg] + hi_s[gg]);
}

// ======================= launch =================================================
extern "C" void kernel_launch(void* const* d_in, const int* in_sizes, int n_in,
                              void* d_out, int out_size) {
  const float* omega  = (const float*)d_in[0];
  const float* Phi    = (const float*)d_in[1];
  const float* metric = (const float*)d_in[2];
  int n = in_sizes[2] / 49;
  if (n > NMAX) n = NMAX;

  float* out = (float*)d_out;
  int oE = out_size - 77;
  int oM = oE - 77 * 77;
  int writeY = (out_size >= 33957 + 77 * 77 + 77) ? 1 : 0;

  int chunk = (n + NGRID - 1) / NGRID;
  cudaFuncSetAttribute(k_main, cudaFuncAttributeMaxDynamicSharedMemorySize,
                       SMEM_MAIN);
  k_main<<<NGRID, 512, SMEM_MAIN>>>(omega, Phi, metric, n, chunk);

  k_reduceS<<<dim3((NPAIR * 20 + 127) / 128, NRED), 128>>>();
  k_emitY<<<(441 * 77 + 255) / 256, 256>>>(out, writeY);

  k_buildM<<<77, 128>>>(out, oM);
  k_eig<<<1, 1024>>>(out, oE);
}

// round 17
// speedup vs baseline: 1.2958x; 1.0553x over previous
#include <cuda_runtime.h>
#include <cuda_bf16.h>
#include <math.h>
#include <stdint.h>

// ======================= compile-time structure constants =======================
struct Tables {
  signed char   ta[35][6];
  signed char   tb[35][6];
  float         ts[35][6];
  unsigned char p2i[256];
  unsigned char p2j[256];
};

constexpr Tables makeTables() {
  Tables T{};
  int c = 0;
  for (int x = 0; x < 7; x++)
    for (int y = x + 1; y < 7; y++)
      for (int z = y + 1; z < 7; z++) {
        int comp[4] = {0, 0, 0, 0};
        int m = 0;
        for (int e = 0; e < 7; e++)
          if (e != x && e != y && e != z) comp[m++] = e;
        int t = 0;
        for (int u = 0; u < 4; u++)
          for (int v = u + 1; v < 4; v++) {
            int a0 = comp[u], a1 = comp[v];
            int b0 = -1, b1 = -1;
            for (int e = 0; e < 4; e++) {
              if (e != u && e != v) { if (b0 < 0) b0 = comp[e]; else b1 = comp[e]; }
            }
            int perm[7] = {a0, a1, b0, b1, x, y, z};
            int inv = 0;
            for (int q = 0; q < 7; q++)
              for (int r = q + 1; r < 7; r++)
                if (perm[q] > perm[r]) inv++;
            T.ts[c][t] = (inv & 1) ? -1.0f : 1.0f;
            T.ta[c][t] = (signed char)(6 * a0 - a0 * (a0 - 1) / 2 + (a1 - a0 - 1));
            T.tb[c][t] = (signed char)(6 * b0 - b0 * (b0 - 1) / 2 + (b1 - b0 - 1));
            t++;
          }
        c++;
      }
  int p = 0;
  for (int i = 0; i < 21; i++)
    for (int j = i; j < 21; j++) {
      T.p2i[p] = (unsigned char)i;
      T.p2j[p] = (unsigned char)j;
      p++;
    }
  for (; p < 256; p++) { T.p2i[p] = 0; T.p2j[p] = 0; }
  return T;
}

constexpr Tables hT = makeTables();
__constant__ Tables dT = makeTables();

// ======================= device scratch =========================================
#define NMAX   4096
#define NGRID  148
#define NPAIR  231
#define NK     77
#define TLD    79
#define NRED   8

__device__ float g_psum[NGRID];
__device__ float g_invsum;
__device__ float g_part[NGRID][256 * 80];
__device__ float g_S8[NRED][NPAIR * 80];
__device__ float g_S[NPAIR * NK];
__device__ float g_A[NK * NK];

// ======================= helpers ================================================
__device__ __forceinline__ uint32_t cvta_smem(const void* p) {
  uint32_t a;
  asm("{ .reg .u64 t; cvta.to.shared.u64 t, %1; cvt.u32.u64 %0, t; }"
      : "=r"(a) : "l"(p));
  return a;
}

__device__ __forceinline__ uint32_t bf16x2pack(float lo, float hi) {
  uint32_t r;
  asm("cvt.rn.bf16x2.f32 %0, %1, %2;" : "=r"(r) : "f"(hi), "f"(lo));
  return r;
}

#define LDSM_X4(r0, r1, r2, r3, addr) \
  asm volatile("ldmatrix.sync.aligned.m8n8.x4.shared.b16 {%0,%1,%2,%3}, [%4];" \
               : "=r"(r0), "=r"(r1), "=r"(r2), "=r"(r3) : "r"(addr))

#define MMA_BF16(c, a, b0_, b1_) \
  asm volatile("mma.sync.aligned.m16n8k16.row.col.f32.bf16.bf16.f32 " \
               "{%0,%1,%2,%3}, {%4,%5,%6,%7}, {%8,%9}, {%0,%1,%2,%3};" \
               : "+f"((c)[0]), "+f"((c)[1]), "+f"((c)[2]), "+f"((c)[3]) \
               : "r"((a)[0]), "r"((a)[1]), "r"((a)[2]), "r"((a)[3]), \
                 "r"(b0_), "r"(b1_))

// smem layout bytes (k_main)
#define AROW      80
#define A_BYTES   (256 * AROW)
#define B_BYTES   (80 * AROW)
#define OFF_B     (2 * A_BYTES)
#define OFF_PF    (OFF_B + 4 * B_BYTES)
#define OFF_DS    (OFF_PF + 2 * 240 * 4)
#define OFF_WS    (OFF_DS + 3 * 256 * 4)
#define SMEM_MAIN (OFF_WS + 2 * 448 * 4)

// ======================= D-compute: fully unrolled ==============================
template <int C, int T>
__device__ __forceinline__ float dterms(const float (&wi)[21], const float (&wj)[21],
                                        float acc) {
  constexpr int a = hT.ta[C][T];
  constexpr int b = hT.tb[C][T];
  if constexpr (hT.ts[C][T] > 0.f)
    acc = fmaf(wi[a], wj[b], acc);
  else
    acc = fmaf(-wi[a], wj[b], acc);
  if constexpr (T + 1 < 6) return dterms<C, T + 1>(wi, wj, acc);
  return acc;
}

template <int U, int UEND>
__device__ __forceinline__ void dBf16(char* smc, uint32_t rowOff,
                                      const float (&wi)[21], const float (&wj)[21]) {
  float d0 = dterms<2 * U, 0>(wi, wj, 0.0f);
  float d1 = dterms<2 * U + 1, 0>(wi, wj, 0.0f);
  uint32_t hw = bf16x2pack(d0, d1);
  float r0 = d0 - __uint_as_float(hw << 16);
  float r1 = d1 - __uint_as_float(hw & 0xffff0000u);
  uint32_t lw = bf16x2pack(r0, r1);
  *(uint32_t*)(smc + rowOff + 4 * U) = hw;
  *(uint32_t*)(smc + A_BYTES + rowOff + 4 * U) = lw;
  if constexpr (U + 1 < UEND) dBf16<U + 1, UEND>(smc, rowOff, wi, wj);
}

template <int C, int CEND>
__device__ __forceinline__ void dF32(float* ds, int pair,
                                     const float (&wi)[21], const float (&wj)[21]) {
  ds[(C - 32) * 256 + pair] = dterms<C, 0>(wi, wj, 0.0f);
  if constexpr (C + 1 < CEND) dF32<C + 1, CEND>(ds, pair, wi, wj);
}

// ======================= kernel 1: hybrid HMMA GEMM + inlined vols ==============
__global__ void __launch_bounds__(512, 1)
k_main(const float* __restrict__ omega, const float* __restrict__ Phi,
       const float* __restrict__ metric, int n, int chunk) {
  extern __shared__ char smc[];
  __shared__ float wv[32];
  const int tid  = threadIdx.x;
  const int w    = tid >> 5;
  const int lane = tid & 31;
  const uint32_t smb = cvta_smem(smc);

  for (int i = tid; i < SMEM_MAIN / 4; i += 512) ((uint32_t*)smc)[i] = 0u;

  int n0 = blockIdx.x * chunk;
  int n1 = n0 + chunk;
  if (n1 > n) n1 = n;

  if (n0 >= n1) {
    if (tid == 0) g_psum[blockIdx.x] = 0.f;
    __syncthreads();
    for (int i = tid; i < 256 * 80; i += 512) g_part[blockIdx.x][i] = 0.f;
    return;
  }

  const int cnt = n1 - n0;
  float myVol = 0.f;
  if (tid < cnt) {
    const float* mp = metric + (size_t)(n0 + tid) * 49;
    float a[7][7];
#pragma unroll
    for (int r = 0; r < 7; r++)
#pragma unroll
      for (int cc = 0; cc < 7; cc++) a[r][cc] = mp[r * 7 + cc];
    float det = 1.f;
#pragma unroll
    for (int k = 0; k < 7; k++) {
      float mx = fabsf(a[k][k]);
      int piv = k;
#pragma unroll
      for (int r = k + 1; r < 7; r++) {
        float v = fabsf(a[r][k]);
        if (v > mx) { mx = v; piv = r; }
      }
#pragma unroll
      for (int r = k + 1; r < 7; r++) {
        if (piv == r) {
          det = -det;
#pragma unroll
          for (int cc = k; cc < 7; cc++) {
            float t = a[k][cc]; a[k][cc] = a[r][cc]; a[r][cc] = t;
          }
        }
      }
      float akk = a[k][k];
      det *= akk;
      float inv = (akk != 0.f) ? 1.f / akk : 0.f;
#pragma unroll
      for (int r = k + 1; r < 7; r++) {
        float f = a[r][k] * inv;
#pragma unroll
        for (int cc = k + 1; cc < 7; cc++) a[r][cc] = fmaf(-f, a[k][cc], a[r][cc]);
      }
    }
    myVol = sqrtf(fabsf(det));
    wv[tid] = myVol;
  }
  if (w == 0) {
    float s = myVol;
#pragma unroll
    for (int o = 16; o; o >>= 1) s += __shfl_xor_sync(0xffffffffu, s, o);
    if (lane == 0) g_psum[blockIdx.x] = s;
  }

  const int myPair = w * 16 + (lane & 15);
  const int pi = dT.p2i[myPair];
  const int pj = dT.p2j[myPair];
  const int halfHi = lane >> 4;
  const int g = lane >> 2;
  const int t = lane & 3;

  uint32_t bOff[6];
  bool bAct[6], bIsB[6];
#pragma unroll
  for (int j = 0; j < 6; j++) {
    int idx = tid + j * 512;
    bAct[j] = idx < 2695;
    int k = idx / 35;
    int c = idx - k * 35;
    bIsB[j] = c < 32;
    bOff[j] = bIsB[j] ? (uint32_t)(k * AROW + c * 2)
                      : (uint32_t)((c - 32) * 80 + k);
  }

  const uint32_t aRow  = (uint32_t)(w * 16 + ((lane >> 3) & 1) * 8 + (lane & 7));
  const uint32_t aAddr = smb + aRow * AROW + (uint32_t)(lane >> 4) * 16;
  const uint32_t bRow  = (uint32_t)(((lane >> 4) & 1) * 8 + (lane & 7));
  const uint32_t bAddr0 = smb + OFF_B + bRow * AROW +
                          (uint32_t)((lane >> 3) & 1) * 16;

  float acc[10][4];
#pragma unroll
  for (int a = 0; a < 10; a++)
#pragma unroll
    for (int b = 0; b < 4; b++) acc[a][b] = 0.f;

  __syncthreads();

  float rO = 0.f, rP[6], rWn = 0.f;
#pragma unroll
  for (int j = 0; j < 6; j++) rP[j] = 0.f;
  {
    const float* og = omega + (size_t)n0 * 441;
    if (tid < 441) rO = og[tid];
    const float* pg = Phi + (size_t)n0 * 2695;
#pragma unroll
    for (int j = 0; j < 6; j++)
      if (bAct[j]) rP[j] = pg[tid + j * 512];
    rWn = wv[0];
  }

  int buf = 0;
#pragma unroll 1
  for (int nn = n0; nn < n1; nn++) {
    char*  bb = smc + OFF_B + (buf ? 2 * B_BYTES : 0);
    float* pf = (float*)(smc + OFF_PF) + (buf ? 240 : 0);
    float* Ws = (float*)(smc + OFF_WS) + (buf ? 448 : 0);
    float* ds = (float*)(smc + OFF_DS);

    if (tid < 441) Ws[tid] = rO;
    {
      const float wn = rWn;
#pragma unroll
      for (int j = 0; j < 6; j++) {
        if (bAct[j]) {
          float v = rP[j] * wn;
          if (bIsB[j]) {
            __nv_bfloat16 bh = __float2bfloat16(v);
            float res = v - __bfloat162float(bh);
            __nv_bfloat16 bl = __float2bfloat16(res);
            *(__nv_bfloat16*)(bb + bOff[j]) = bh;
            *(__nv_bfloat16*)(bb + B_BYTES + bOff[j]) = bl;
          } else {
            pf[bOff[j]] = v;
          }
        }
      }
    }

    {
      int nx = (nn + 1 < n1) ? nn + 1 : nn;
      const float* og = omega + (size_t)nx * 441;
      if (tid < 441) rO = og[tid];
      const float* pg = Phi + (size_t)nx * 2695;
#pragma unroll
      for (int j = 0; j < 6; j++)
        if (bAct[j]) rP[j] = pg[tid + j * 512];
      rWn = wv[nx - n0];
    }
    __syncthreads();

    __syncwarp();
    {
      float wi[21], wj[21];
      const float* Wi = &Ws[pi * 21];
      const float* Wj = &Ws[pj * 21];
#pragma unroll
      for (int a = 0; a < 21; a++) { wi[a] = Wi[a]; wj[a] = Wj[a]; }
      const uint32_t rowOff = (uint32_t)(myPair * AROW);
      if (!halfHi) {
        dBf16<0, 9>(smc, rowOff, wi, wj);
      } else {
        dBf16<9, 16>(smc, rowOff, wi, wj);
        dF32<32, 35>(ds, myPair, wi, wj);
      }
    }
    __syncwarp();

    const uint32_t bAddr = bAddr0 + (buf ? (uint32_t)(2 * B_BYTES) : 0u);
#pragma unroll
    for (int ks = 0; ks < 2; ks++) {
      uint32_t ah[4], al[4];
      LDSM_X4(ah[0], ah[1], ah[2], ah[3], aAddr + ks * 32);
      LDSM_X4(al[0], al[1], al[2], al[3], aAddr + A_BYTES + ks * 32);
#pragma unroll
      for (int tp = 0; tp < 5; tp++) {
        uint32_t bh[4], bl[4];
        uint32_t ba = bAddr + (uint32_t)(tp * 16 * AROW) + ks * 32;
        LDSM_X4(bh[0], bh[1], bh[2], bh[3], ba);
        LDSM_X4(bl[0], bl[1], bl[2], bl[3], ba + B_BYTES);
        MMA_BF16(acc[2 * tp],     ah, bh[0], bh[1]);
        MMA_BF16(acc[2 * tp],     ah, bl[0], bl[1]);
        MMA_BF16(acc[2 * tp],     al, bh[0], bh[1]);
        MMA_BF16(acc[2 * tp + 1], ah, bh[2], bh[3]);
        MMA_BF16(acc[2 * tp + 1], ah, bl[2], bl[3]);
        MMA_BF16(acc[2 * tp + 1], al, bh[2], bh[3]);
      }
    }

    {
      const int base = w * 16 + g;
#pragma unroll
      for (int c2 = 0; c2 < 3; c2++) {
        float dr0 = ds[c2 * 256 + base];
        float dr1 = ds[c2 * 256 + base + 8];
        const float* prow = &pf[c2 * 80 + 2 * t];
#pragma unroll
        for (int nt = 0; nt < 10; nt++) {
          float2 pv = *(const float2*)&prow[nt * 8];
          acc[nt][0] = fmaf(dr0, pv.x, acc[nt][0]);
          acc[nt][1] = fmaf(dr0, pv.y, acc[nt][1]);
          acc[nt][2] = fmaf(dr1, pv.x, acc[nt][2]);
          acc[nt][3] = fmaf(dr1, pv.y, acc[nt][3]);
        }
      }
    }
    buf ^= 1;
  }

  {
    const int r0 = w * 16 + g, r1 = r0 + 8;
    float* dst = g_part[blockIdx.x];
#pragma unroll
    for (int nt = 0; nt < 10; nt++) {
      int col = nt * 8 + 2 * t;
      *(float2*)&dst[r0 * 80 + col] = make_float2(acc[nt][0], acc[nt][1]);
      *(float2*)&dst[r1 * 80 + col] = make_float2(acc[nt][2], acc[nt][3]);
    }
  }
}

// ======================= kernel 2a: reduce partials + invsum ====================
__global__ void __launch_bounds__(128, 8)
k_reduceS() {
  if (blockIdx.x == 0 && blockIdx.y == 0 && threadIdx.x < 32) {
    float s = 0.f;
    for (int i = threadIdx.x; i < NGRID; i += 32) s += g_psum[i];
#pragma unroll
    for (int o = 16; o; o >>= 1) s += __shfl_xor_sync(0xffffffffu, s, o);
    if (threadIdx.x == 0) g_invsum = 1.f / s;
  }
  const int t = blockIdx.x * 128 + threadIdx.x;
  if (t >= NPAIR * 20) return;
  const int p = t / 20;
  const int q = t - p * 20;
  const int y = blockIdx.y;
  const int b0  = (y < 4) ? y * 19 : 76 + (y - 4) * 18;
  const int cnt = (y < 4) ? 19 : 18;
  float4 s = make_float4(0.f, 0.f, 0.f, 0.f);
#pragma unroll 4
  for (int b = 0; b < cnt; b++) {
    float4 v = *(const float4*)&g_part[b0 + b][p * 80 + q * 4];
    s.x += v.x; s.y += v.y; s.z += v.z; s.w += v.w;
  }
  *(float4*)&g_S8[y][p * 80 + q * 4] = s;
}

// ======================= kernel 2b: emit Y + final S ============================
__global__ void k_emitY(float* __restrict__ out, int writeY) {
  int idx = blockIdx.x * blockDim.x + threadIdx.x;
  if (idx >= 441 * 77) return;
  const float inv = g_invsum;
  int i = idx / 1617;
  int rem = idx - i * 1617;
  int j = rem / 77;
  int k = rem - j * 77;
  int lo = i < j ? i : j;
  int hi = i < j ? j : i;
  int p = lo * 21 - lo * (lo - 1) / 2 + (hi - lo);
  int o = p * 80 + k;
  float s = ((g_S8[0][o] + g_S8[1][o]) + (g_S8[2][o] + g_S8[3][o])) +
            ((g_S8[4][o] + g_S8[5][o]) + (g_S8[6][o] + g_S8[7][o]));
  s *= inv;
  if (writeY) out[idx] = (j >= i) ? s : -s;
  if (i <= j) g_S[p * 77 + k] = s;
}

// ======================= kernel 3: build M (6-way p-split, 512 thr) =============
__global__ void __launch_bounds__(512, 1)
k_buildM(float* __restrict__ out, int oM) {
  __shared__ float cs[NPAIR];
  __shared__ float part[6][80];
  const int k = blockIdx.x;
  const int tid = threadIdx.x;
  for (int p = tid; p < NPAIR; p += 512) {
    float wgt = (dT.p2i[p] == dT.p2j[p]) ? 1.f : 2.f;
    cs[p] = wgt * g_S[p * 77 + k];
  }
  __syncthreads();
  const int grp = tid / 77;
  const int col = tid - grp * 77;
  if (grp < 6) {
    int p0 = grp * 39;
    int p1 = p0 + 39;
    if (p1 > NPAIR) p1 = NPAIR;
    float a0 = 0.f, a1 = 0.f, a2 = 0.f;
    int p = p0;
    for (; p + 3 <= p1; p += 3) {
      a0 = fmaf(cs[p],     g_S[p * 77 + col],       a0);
      a1 = fmaf(cs[p + 1], g_S[(p + 1) * 77 + col], a1);
      a2 = fmaf(cs[p + 2], g_S[(p + 2) * 77 + col], a2);
    }
    for (; p < p1; p++) a0 = fmaf(cs[p], g_S[p * 77 + col], a0);
    part[grp][col] = (a0 + a1) + a2;
  }
  __syncthreads();
  if (tid < 77) {
    float v = ((part[0][tid] + part[1][tid]) + (part[2][tid] + part[3][tid])) +
              (part[4][tid] + part[5][tid]);
    out[oM + k * 77 + tid] = v;
    g_A[k * 77 + tid] = v;
  }
}

// ======================= kernel 4: tridiag (3 barriers/step) + Sturm bisect =====
#define NPROBE 13
#define NROUND 9

__global__ void __launch_bounds__(1024, 1)
k_eig(float* __restrict__ out, int oE) {
  __shared__ float A[NK * TLD];
  __shared__ float us[80], pp[80];
  __shared__ float dd[NK], ee[NK], e2s[NK];
  __shared__ float lo_s[NK], hi_s[NK];
  __shared__ float xs[NK * NPROBE];
  __shared__ int   cs[NK * NPROBE];
  __shared__ float gl_s, gh_s, piv_s;
  const int tid  = threadIdx.x;
  const int lane = tid & 31;
  const int warp = tid >> 5;
  const int rrow = tid >> 3;
  const int rq   = tid & 7;

  for (int idx = tid; idx < NK * NK; idx += 1024) {
    int r = idx / NK, c = idx - r * NK;
    A[r * TLD + c] = g_A[idx];
  }
  __syncthreads();

#pragma unroll 1
  for (int k = 0; k < 75; k++) {
    const int m = 76 - k;

    // Phase A (every warp, redundant -> bit-identical): sigma, alpha, scTb
    float v0s = 0.f, v1s = 0.f, v2s = 0.f;
    if (lane < m)      v0s = A[(k + 1 + lane) * TLD + k];
    if (lane + 32 < m) v1s = A[(k + 33 + lane) * TLD + k];
    if (lane + 64 < m) v2s = A[(k + 65 + lane) * TLD + k];
    float sig = v0s * v0s + v1s * v1s + v2s * v2s;
#pragma unroll
    for (int o = 16; o; o >>= 1) sig += __shfl_xor_sync(0xffffffffu, sig, o);
    float v0 = __shfl_sync(0xffffffffu, v0s, 0);
    const bool skip = (sig < 1e-30f);
    float scTb = 0.f;
    if (!skip) {
      float alpha = -copysignf(sqrtf(sig), v0);
      scTb = 2.f / (2.f * (sig - v0 * alpha));
      if (warp == 0) {
        if (lane == 0) { dd[k] = A[k * TLD + k]; ee[k] = alpha; }
        if (lane < m)      us[lane]      = (lane == 0) ? v0s - alpha : v0s;
        if (lane + 32 < m) us[lane + 32] = v1s;
        if (lane + 64 < m) us[lane + 64] = v2s;
      }
    } else {
      if (warp == 0 && lane == 0) { dd[k] = A[k * TLD + k]; ee[k] = 0.f; }
    }
    if (skip) continue;
    __syncthreads();      // B1: us visible

    // Phase B (all): matvec pp = scTb * A(sub) * u, 8 threads per row
    {
      float a0 = 0.f, a1 = 0.f;
      if (rrow < m) {
        const float* row = &A[(k + 1 + rrow) * TLD + (k + 1)];
        int j = rq;
        for (; j + 8 < m; j += 16) {
          a0 = fmaf(row[j],     us[j],     a0);
          a1 = fmaf(row[j + 8], us[j + 8], a1);
        }
        for (; j < m; j += 8) a0 = fmaf(row[j], us[j], a0);
      }
      float s = a0 + a1;
      s += __shfl_xor_sync(0xffffffffu, s, 1);
      s += __shfl_xor_sync(0xffffffffu, s, 2);
      s += __shfl_xor_sync(0xffffffffu, s, 4);
      if (rrow < m && rq == 0) pp[rrow] = s * scTb;
    }
    __syncthreads();      // B2: pp visible

    // Phase C (all): per-warp redundant kappa; rank-2 with register j-operands
    {
      const bool a0ok = (lane < m), a1ok = (lane + 32 < m), a2ok = (lane + 64 < m);
      float p0 = 0.f, p1 = 0.f, p2 = 0.f;
      float u0 = 0.f, u1 = 0.f, u2 = 0.f;
      if (a0ok) { p0 = pp[lane];      u0 = us[lane]; }
      if (a1ok) { p1 = pp[lane + 32]; u1 = us[lane + 32]; }
      if (a2ok) { p2 = pp[lane + 64]; u2 = us[lane + 64]; }
      float t = p0 * u0 + p1 * u1 + p2 * u2;
#pragma unroll
      for (int o = 16; o; o >>= 1) t += __shfl_xor_sync(0xffffffffu, t, o);
      const float twoKappa = t * scTb;
      // A_ij -= u_i*pp_j + (pp_i - 2k*u_i)*u_j ; j-operands live in registers
      for (int i = warp; i < m; i += 32) {
        const float ui = us[i];
        const float qi = pp[i] - twoKappa * ui;
        float* rowA = &A[(k + 1 + i) * TLD + (k + 1)];
        if (a0ok) rowA[lane]      -= ui * p0 + qi * u0;
        if (a1ok) rowA[lane + 32] -= ui * p1 + qi * u1;
        if (a2ok) rowA[lane + 64] -= ui * p2 + qi * u2;
      }
    }
    __syncthreads();      // B3: A updated
  }

  if (tid == 0) {
    dd[75] = A[75 * TLD + 75];
    ee[75] = A[76 * TLD + 75];
    dd[76] = A[76 * TLD + 76];
    ee[76] = 0.f;
  }
  __syncthreads();
  if (tid < NK) e2s[tid] = ee[tid] * ee[tid];
  __syncthreads();

  // ---- Sturm multisection eigenvalues ----
  if (tid == 0) {
    float gl = 3.4e38f, gh = -3.4e38f, me2 = 0.f;
    for (int i = 0; i < NK; i++) {
      float eprev = (i > 0) ? sqrtf(e2s[i - 1]) : 0.f;
      float ecur  = (i < 76) ? sqrtf(e2s[i]) : 0.f;
      float r = eprev + ecur;
      gl = fminf(gl, dd[i] - r);
      gh = fmaxf(gh, dd[i] + r);
      me2 = fmaxf(me2, e2s[i]);
    }
    float wid = fmaxf(gh - gl, 1e-20f);
    gl_s = gl - 1e-3f * wid;
    gh_s = gh + 1e-3f * wid;
    piv_s = fmaxf(me2 * 1.2e-38f, 1e-37f);
  }
  __syncthreads();
  if (tid < NK) { lo_s[tid] = gl_s; hi_s[tid] = gh_s; }
  __syncthreads();

  const int gg = tid / NPROBE;
  const int jj = tid - gg * NPROBE;
  const bool act = (gg < NK);
  const float pivmin = piv_s;
  const float cj = (float)(jj + 1) / (float)(NPROBE + 1);

#pragma unroll 1
  for (int r = 0; r < NROUND; r++) {
    if (act) {
      float lo = lo_s[gg], hi = hi_s[gg];
      float x = lo + (hi - lo) * cj;
      xs[tid] = x;
      float q = dd[0] - x;
      int cnt = (q < 0.f);
#pragma unroll 4
      for (int i = 1; i < NK; i++) {
        float aq = fabsf(q);
        if (aq < pivmin) q = -pivmin;
        q = dd[i] - x - __fdividef(e2s[i - 1], q);
        cnt += (q < 0.f);
      }
      cs[tid] = cnt;
    }
    __syncthreads();
    if (act && jj == 0) {
      float lo = lo_s[gg], hi = hi_s[gg];
      for (int u = 0; u < NPROBE; u++) {
        int c = cs[gg * NPROBE + u];
        float x = xs[gg * NPROBE + u];
        if (c <= gg) lo = x;
        else { hi = x; break; }
      }
      lo_s[gg] = lo;
      hi_s[gg] = hi;
    }
    __syncthreads();
  }

  if (act && jj == 0) out[oE + (76 - gg)] = 0.5f * (lo_s[gg] + hi_s[gg]);
}

// ======================= launch =================================================
extern "C" void kernel_launch(void* const* d_in, const int* in_sizes, int n_in,
                              void* d_out, int out_size) {
  const float* omega  = (const float*)d_in[0];
  const float* Phi    = (const float*)d_in[1];
  const float* metric = (const float*)d_in[2];
  int n = in_sizes[2] / 49;
  if (n > NMAX) n = NMAX;

  float* out = (float*)d_out;
  int oE = out_size - 77;
  int oM = oE - 77 * 77;
  int writeY = (out_size >= 33957 + 77 * 77 + 77) ? 1 : 0;

  int chunk = (n + NGRID - 1) / NGRID;
  cudaFuncSetAttribute(k_main, cudaFuncAttributeMaxDynamicSharedMemorySize,
                       SMEM_MAIN);
  k_main<<<NGRID, 512, SMEM_MAIN>>>(omega, Phi, metric, n, chunk);

  k_reduceS<<<dim3((NPAIR * 20 + 127) / 128, NRED), 128>>>();
  k_emitY<<<(441 * 77 + 255) / 256, 256>>>(out, writeY);

  k_buildM<<<77, 512>>>(out, oM);
  k_eig<<<1, 1024>>>(out, oE);
}